// round 13
// baseline (speedup 1.0000x reference)
#include <cuda_runtime.h>
#include <math.h>

#define NN 50000
#define NE 800000
#define NG 64
#define SLOT 96

typedef unsigned long long u64;
typedef unsigned int u32;

// ------------------- scratch (device globals; zero-initialized at load) ----
__device__ float d_xl1[NN * 256];
__device__ float d_h1 [NN * 256];
__device__ float d_xl2[NN * 128];
__device__ float d_xr2[NN * 128];
__device__ float d_h2 [NN * 128];
__device__ int   d_cursor[NN];
__device__ u64   d_sadj[(size_t)NN * SLOT];   // packed (ea:f32 hi, src:i32 lo)
__device__ float d_pool[NG * 128];
__device__ float d_cnt[NG];

// ---------------- packed f32x2 helpers --------------------------------------
__device__ __forceinline__ u64 pk2(float lo, float hi) {
    u64 r; asm("mov.b64 %0, {%1,%2};" : "=l"(r) : "f"(lo), "f"(hi)); return r;
}
__device__ __forceinline__ void upk2(u64 v, float& lo, float& hi) {
    asm("mov.b64 {%0,%1}, %2;" : "=f"(lo), "=f"(hi) : "l"(v));
}
__device__ __forceinline__ u64 add2(u64 a, u64 b) {
    u64 d; asm("add.rn.f32x2 %0, %1, %2;" : "=l"(d) : "l"(a), "l"(b)); return d;
}
__device__ __forceinline__ u64 mul2(u64 a, u64 b) {
    u64 d; asm("mul.rn.f32x2 %0, %1, %2;" : "=l"(d) : "l"(a), "l"(b)); return d;
}
__device__ __forceinline__ u64 fma2(u64 a, u64 b, u64 c) {
    u64 d; asm("fma.rn.f32x2 %0, %1, %2, %3;" : "=l"(d) : "l"(a), "l"(b), "l"(c)); return d;
}
#define ABS2 0x7FFFFFFF7FFFFFFFull

// packed GATv2 logit contribution: t = leaky(l + xr + eav*we); lg += t*at
__device__ __forceinline__ u64 gat2(u64 l, u64 xr, u64 we, u64 at, u64 eav2,
                                    u64 c06, u64 c04, u64 lg) {
    u64 t = add2(l, xr);
    t = fma2(eav2, we, t);
    u64 ab = t & ABS2;
    t = fma2(c04, ab, mul2(t, c06));    // = m>0 ? m : 0.2m
    return fma2(t, at, lg);
}

// safe exp: logits here are O(10); clamp is a never-hit overflow guard
__device__ __forceinline__ float sexp(float a) { return __expf(fminf(a, 80.f)); }

// ---------------------------------------------------------------------------
// FUSED: gemm1 (xl1 = x @ Wl1) + adjacency fill, split by block role
#define GEMM1_BLKS (NN / 4)           // 12500
#define FILL_BLKS  ((NE + 255) / 256) // 3125
__global__ void k_gfill(const float* __restrict__ x, const float* __restrict__ Wl,
                        const int* __restrict__ ei, const float* __restrict__ ea) {
    int tid = threadIdx.x;
    if (blockIdx.x < GEMM1_BLKS) {
        __shared__ float sx[32];
        int n0 = blockIdx.x * 4;
        if (tid < 32) sx[tid] = x[n0 * 8 + tid];
        __syncthreads();
        float w[8];
#pragma unroll
        for (int k = 0; k < 8; k++) w[k] = Wl[k * 256 + tid];
#pragma unroll
        for (int q = 0; q < 4; q++) {
            float a = 0.f;
#pragma unroll
            for (int k = 0; k < 8; k++) a += sx[q * 8 + k] * w[k];
            d_xl1[(size_t)(n0 + q) * 256 + tid] = a;
        }
    } else {
        int e = (blockIdx.x - GEMM1_BLKS) * 256 + tid;
        if (e < NE) {
            int dst = ei[NE + e];
            int src = ei[e];
            float v = ea[e];
            int p = atomicAdd(&d_cursor[dst], 1);
            if (p < SLOT)
                d_sadj[(size_t)dst * SLOT + p] =
                    ((u64)__float_as_uint(v) << 32) | (u32)src;
        }
    }
}

// ======== layer-1 FUSED, warp per node, unnormalized-exp softmax ============
// Lane owns channels [lane*8, lane*8+8); head = lane>>3 (8-lane segments).
// Self-loop processed LAST (order-free with unnormalized exp); loopv computed
// from easum accumulated in the edge loop (eav is warp-uniform).
__global__ __launch_bounds__(256, 4) void
k_fagg1(const float* __restrict__ x,
        const float* __restrict__ Wr, const float* __restrict__ We,
        const float* __restrict__ att,
        const float* __restrict__ b1, const float* __restrict__ g1,
        const float* __restrict__ beta1) {
    int wid = threadIdx.x >> 5, lane = threadIdx.x & 31;
    int n = blockIdx.x * 8 + wid;

    int cnt = d_cursor[n];
    if (cnt > SLOT) cnt = SLOT;

    int c0 = lane * 8;

    // xr row: x[n] (8) @ Wr (8x256), this lane's 8 channels (scalar, then pack)
    float xv = (lane < 8) ? x[n * 8 + lane] : 0.f;
    float xr[8];
#pragma unroll
    for (int j = 0; j < 8; j++) xr[j] = 0.f;
#pragma unroll
    for (int k = 0; k < 8; k++) {
        float xk = __shfl_sync(0xffffffffu, xv, k);
        float4 wA = __ldg((const float4*)(Wr + k * 256 + c0));
        float4 wB = __ldg((const float4*)(Wr + k * 256 + c0 + 4));
        xr[0] += xk * wA.x; xr[1] += xk * wA.y; xr[2] += xk * wA.z; xr[3] += xk * wA.w;
        xr[4] += xk * wB.x; xr[5] += xk * wB.y; xr[6] += xk * wB.z; xr[7] += xk * wB.w;
    }
    u64 xr2[4];
#pragma unroll
    for (int p = 0; p < 4; p++) xr2[p] = pk2(xr[2 * p], xr[2 * p + 1]);

    ulonglong2 weL = *(const ulonglong2*)(We + c0);
    ulonglong2 weH = *(const ulonglong2*)(We + c0 + 4);
    ulonglong2 atL = *(const ulonglong2*)(att + c0);
    ulonglong2 atH = *(const ulonglong2*)(att + c0 + 4);
    u64 we2[4] = {weL.x, weL.y, weH.x, weH.y};
    u64 at2[4] = {atL.x, atL.y, atH.x, atH.y};
    const u64 c06 = pk2(0.6f, 0.6f), c04 = pk2(0.4f, 0.4f);

    u64 accp[4] = {0ull, 0ull, 0ull, 0ull};
    float dsum = 0.f, easum = 0.f;

    const size_t sbase = (size_t)n * SLOT;
    int i = 0;
    // ---- pairs of edges (iterations fully independent) ----
    for (; i + 1 < cnt; i += 2) {
        ulonglong2 pp = *(const ulonglong2*)(d_sadj + sbase + i);
        int   src1 = (int)(u32)pp.x; float ea1 = __uint_as_float((u32)(pp.x >> 32));
        int   src2 = (int)(u32)pp.y; float ea2 = __uint_as_float((u32)(pp.y >> 32));
        const ulonglong2* p1 = (const ulonglong2*)(d_xl1 + (size_t)src1 * 256 + c0);
        const ulonglong2* p2 = (const ulonglong2*)(d_xl1 + (size_t)src2 * 256 + c0);
        ulonglong2 l1a = p1[0], l1b = p1[1];
        ulonglong2 l2a = p2[0], l2b = p2[1];
        u64 l1[4] = {l1a.x, l1a.y, l1b.x, l1b.y};
        u64 l2[4] = {l2a.x, l2a.y, l2b.x, l2b.y};
        u64 ev1 = pk2(ea1, ea1), ev2 = pk2(ea2, ea2);
        easum += ea1 + ea2;
        u64 lg1 = 0ull, lg2 = 0ull;
#pragma unroll
        for (int p = 0; p < 4; p++) {
            lg1 = gat2(l1[p], xr2[p], we2[p], at2[p], ev1, c06, c04, lg1);
            lg2 = gat2(l2[p], xr2[p], we2[p], at2[p], ev2, c06, c04, lg2);
        }
        float lo1, hi1, lo2, hi2;
        upk2(lg1, lo1, hi1); upk2(lg2, lo2, hi2);
        float a1 = lo1 + hi1, a2 = lo2 + hi2;
        a1 += __shfl_xor_sync(0xffffffffu, a1, 1);
        a2 += __shfl_xor_sync(0xffffffffu, a2, 1);
        a1 += __shfl_xor_sync(0xffffffffu, a1, 2);
        a2 += __shfl_xor_sync(0xffffffffu, a2, 2);
        a1 += __shfl_xor_sync(0xffffffffu, a1, 4);
        a2 += __shfl_xor_sync(0xffffffffu, a2, 4);
        float e1 = sexp(a1);
        float e2 = sexp(a2);
        dsum += e1 + e2;
        u64 e12 = pk2(e1, e1), e22 = pk2(e2, e2);
#pragma unroll
        for (int p = 0; p < 4; p++)
            accp[p] = fma2(e22, l2[p], fma2(e12, l1[p], accp[p]));
    }
    // ---- odd tail edge ----
    if (i < cnt) {
        u64 p = d_sadj[sbase + i];
        int src1 = (int)(u32)p; float ea1 = __uint_as_float((u32)(p >> 32));
        const ulonglong2* p1 = (const ulonglong2*)(d_xl1 + (size_t)src1 * 256 + c0);
        ulonglong2 l1a = p1[0], l1b = p1[1];
        u64 l1[4] = {l1a.x, l1a.y, l1b.x, l1b.y};
        u64 ev1 = pk2(ea1, ea1);
        easum += ea1;
        u64 lg1 = 0ull;
#pragma unroll
        for (int q = 0; q < 4; q++) lg1 = gat2(l1[q], xr2[q], we2[q], at2[q], ev1, c06, c04, lg1);
        float lo1, hi1; upk2(lg1, lo1, hi1);
        float a1 = lo1 + hi1;
        a1 += __shfl_xor_sync(0xffffffffu, a1, 1);
        a1 += __shfl_xor_sync(0xffffffffu, a1, 2);
        a1 += __shfl_xor_sync(0xffffffffu, a1, 4);
        float e1 = sexp(a1);
        dsum += e1;
        u64 e12 = pk2(e1, e1);
#pragma unroll
        for (int q = 0; q < 4; q++)
            accp[q] = fma2(e12, l1[q], accp[q]);
    }

    // ---- self-loop last ----
    {
        float loopv = easum / fmaxf((float)cnt, 1.f);
        const ulonglong2* ps = (const ulonglong2*)(d_xl1 + (size_t)n * 256 + c0);
        ulonglong2 s0 = ps[0], s1 = ps[1];
        u64 sl[4] = {s0.x, s0.y, s1.x, s1.y};
        u64 eav2 = pk2(loopv, loopv);
        u64 lg = 0ull;
#pragma unroll
        for (int p = 0; p < 4; p++) lg = gat2(sl[p], xr2[p], we2[p], at2[p], eav2, c06, c04, lg);
        float lo, hi; upk2(lg, lo, hi);
        float a = lo + hi;
        a += __shfl_xor_sync(0xffffffffu, a, 1);
        a += __shfl_xor_sync(0xffffffffu, a, 2);
        a += __shfl_xor_sync(0xffffffffu, a, 4);
        float e0 = sexp(a);
        dsum += e0;
        u64 e02 = pk2(e0, e0);
#pragma unroll
        for (int p = 0; p < 4; p++) accp[p] = fma2(e02, sl[p], accp[p]);
    }

    float inv = 1.f / (dsum + 1e-16f);
    float o[8];
#pragma unroll
    for (int p = 0; p < 4; p++) upk2(accp[p], o[2 * p], o[2 * p + 1]);
    float4 bA = __ldg((const float4*)(b1 + c0));
    float4 bB = __ldg((const float4*)(b1 + c0 + 4));
    o[0] = o[0] * inv + bA.x; o[1] = o[1] * inv + bA.y;
    o[2] = o[2] * inv + bA.z; o[3] = o[3] * inv + bA.w;
    o[4] = o[4] * inv + bB.x; o[5] = o[5] * inv + bB.y;
    o[6] = o[6] * inv + bB.z; o[7] = o[7] * inv + bB.w;

    // LayerNorm(256) across the warp
    float s = 0.f, s2 = 0.f;
#pragma unroll
    for (int j = 0; j < 8; j++) { s += o[j]; s2 += o[j] * o[j]; }
#pragma unroll
    for (int d = 16; d >= 1; d >>= 1) {
        s  += __shfl_xor_sync(0xffffffffu, s, d);
        s2 += __shfl_xor_sync(0xffffffffu, s2, d);
    }
    float mu = s * (1.f / 256.f);
    float var = s2 * (1.f / 256.f) - mu * mu;
    float rstd = rsqrtf(var + 1e-5f);
    float4 gA = __ldg((const float4*)(g1 + c0));
    float4 gB = __ldg((const float4*)(g1 + c0 + 4));
    float4 tA = __ldg((const float4*)(beta1 + c0));
    float4 tB = __ldg((const float4*)(beta1 + c0 + 4));
    float y[8];
    y[0] = (o[0]-mu)*rstd*gA.x + tA.x; y[1] = (o[1]-mu)*rstd*gA.y + tA.y;
    y[2] = (o[2]-mu)*rstd*gA.z + tA.z; y[3] = (o[3]-mu)*rstd*gA.w + tA.w;
    y[4] = (o[4]-mu)*rstd*gB.x + tB.x; y[5] = (o[5]-mu)*rstd*gB.y + tB.y;
    y[6] = (o[6]-mu)*rstd*gB.z + tB.z; y[7] = (o[7]-mu)*rstd*gB.w + tB.w;
#pragma unroll
    for (int j = 0; j < 8; j++) y[j] = (y[j] > 0.f) ? y[j] : (__expf(y[j]) - 1.f);
    float4* ph = (float4*)(d_h1 + (size_t)n * 256 + c0);
    ph[0] = make_float4(y[0], y[1], y[2], y[3]);
    ph[1] = make_float4(y[4], y[5], y[6], y[7]);
}

// ======== GEMM2 via tf32 mma.sync, SMEM-staged + reg prefetch ===============
__device__ __forceinline__ u32 f2tf(float f) {
    u32 u;
    asm("cvt.rna.tf32.f32 %0, %1;" : "=r"(u) : "f"(f));
    return u;
}
__device__ __forceinline__ void mma_tf32(float* d, const u32* a, u32 b0, u32 b1) {
    asm("mma.sync.aligned.m16n8k8.row.col.f32.tf32.tf32.f32 "
        "{%0,%1,%2,%3}, {%4,%5,%6,%7}, {%8,%9}, {%0,%1,%2,%3};"
        : "+f"(d[0]), "+f"(d[1]), "+f"(d[2]), "+f"(d[3])
        : "r"(a[0]), "r"(a[1]), "r"(a[2]), "r"(a[3]), "r"(b0), "r"(b1));
}

#define GK 16
__global__ __launch_bounds__(512) void
k_gemm2(const float* __restrict__ Wl, const float* __restrict__ Wr) {
    __shared__ u32 sA[128][20];
    __shared__ u32 sB[GK][264];
    int tid = threadIdx.x;
    int w = tid >> 5, lane = tid & 31;
    int gid = lane >> 2, tig = lane & 3;
    int mgrp = w >> 2, ngrp = w & 3;
    int row0 = blockIdx.x * 128;
    int wm0 = mgrp * 32;
    int wn0 = ngrp * 64;

    float d[2][8][4];
#pragma unroll
    for (int mt = 0; mt < 2; mt++)
#pragma unroll
        for (int nt = 0; nt < 8; nt++)
#pragma unroll
            for (int q = 0; q < 4; q++) d[mt][nt][q] = 0.f;

    int ar = tid >> 2, akq = tid & 3;
    int gr = min(row0 + ar, NN - 1);
    const float4* aptr = (const float4*)(d_h1 + (size_t)gr * 256 + akq * 4);
    int kr0 = tid >> 6,         cq0 = tid & 63;
    int kr1 = (tid + 512) >> 6, cq1 = (tid + 512) & 63;
    const float* bsrc0 = (cq0 < 32) ? (Wl + kr0 * 128 + cq0 * 4)
                                    : (Wr + kr0 * 128 + (cq0 - 32) * 4);
    const float* bsrc1 = (cq1 < 32) ? (Wl + kr1 * 128 + cq1 * 4)
                                    : (Wr + kr1 * 128 + (cq1 - 32) * 4);

    float4 va = aptr[0];
    float4 vb0 = *(const float4*)bsrc0;
    float4 vb1 = *(const float4*)bsrc1;

    for (int k0 = 0; k0 < 256; k0 += GK) {
        sA[ar][akq * 4 + 0] = f2tf(va.x);
        sA[ar][akq * 4 + 1] = f2tf(va.y);
        sA[ar][akq * 4 + 2] = f2tf(va.z);
        sA[ar][akq * 4 + 3] = f2tf(va.w);
        sB[kr0][cq0 * 4 + 0] = f2tf(vb0.x);
        sB[kr0][cq0 * 4 + 1] = f2tf(vb0.y);
        sB[kr0][cq0 * 4 + 2] = f2tf(vb0.z);
        sB[kr0][cq0 * 4 + 3] = f2tf(vb0.w);
        sB[kr1][cq1 * 4 + 0] = f2tf(vb1.x);
        sB[kr1][cq1 * 4 + 1] = f2tf(vb1.y);
        sB[kr1][cq1 * 4 + 2] = f2tf(vb1.z);
        sB[kr1][cq1 * 4 + 3] = f2tf(vb1.w);
        __syncthreads();
        if (k0 + GK < 256) {
            va  = aptr[(k0 + GK) >> 2];
            vb0 = *(const float4*)(bsrc0 + (size_t)(k0 + GK) * 128);
            vb1 = *(const float4*)(bsrc1 + (size_t)(k0 + GK) * 128);
        }
#pragma unroll
        for (int kk = 0; kk < GK; kk += 8) {
            u32 a[2][4];
            a[0][0] = sA[wm0 + gid][kk + tig];
            a[0][1] = sA[wm0 + gid + 8][kk + tig];
            a[0][2] = sA[wm0 + gid][kk + tig + 4];
            a[0][3] = sA[wm0 + gid + 8][kk + tig + 4];
            a[1][0] = sA[wm0 + 16 + gid][kk + tig];
            a[1][1] = sA[wm0 + 24 + gid][kk + tig];
            a[1][2] = sA[wm0 + 16 + gid][kk + tig + 4];
            a[1][3] = sA[wm0 + 24 + gid][kk + tig + 4];
#pragma unroll
            for (int nt = 0; nt < 8; nt++) {
                int c = wn0 + nt * 8 + gid;
                u32 b0 = sB[kk + tig][c];
                u32 b1 = sB[kk + tig + 4][c];
                mma_tf32(d[0][nt], a[0], b0, b1);
                mma_tf32(d[1][nt], a[1], b0, b1);
            }
        }
        __syncthreads();
    }

    float* OUT = (wn0 < 128) ? d_xl2 : d_xr2;
#pragma unroll
    for (int mt = 0; mt < 2; mt++) {
        int rA = row0 + wm0 + mt * 16 + gid;
        int rB = rA + 8;
#pragma unroll
        for (int nt = 0; nt < 8; nt++) {
            int cc = (wn0 + nt * 8 + 2 * tig) & 127;
            if (rA < NN)
                *(float2*)(OUT + (size_t)rA * 128 + cc) = make_float2(d[mt][nt][0], d[mt][nt][1]);
            if (rB < NN)
                *(float2*)(OUT + (size_t)rB * 128 + cc) = make_float2(d[mt][nt][2], d[mt][nt][3]);
        }
    }
}

// ======== layer-2 FUSED: 2 nodes per warp, unnormalized-exp softmax =========
// Lane owns 8 channels: c0 = (lane&15)*8 of node (wid*2 + lane>>4).
// launch_bounds(256, 5): push occupancy further (fagg kernels scale w/ warps).
__global__ __launch_bounds__(256, 5) void
k_fagg2(const float* __restrict__ We, const float* __restrict__ att,
        const float* __restrict__ b2, const float* __restrict__ g2,
        const float* __restrict__ beta2) {
    int wid = threadIdx.x >> 5, lane = threadIdx.x & 31;
    int half = lane >> 4, lane16 = lane & 15;
    int n = blockIdx.x * 16 + wid * 2 + half;

    int cnt = d_cursor[n];
    if (cnt > SLOT) cnt = SLOT;
    if (lane16 == 0) d_cursor[n] = 0;   // reset for next replay

    int c0 = lane16 * 8;
    const ulonglong2* pxr = (const ulonglong2*)(d_xr2 + (size_t)n * 128 + c0);
    ulonglong2 xrA = pxr[0], xrB = pxr[1];
    u64 xr2v[4] = {xrA.x, xrA.y, xrB.x, xrB.y};
    ulonglong2 weA = *(const ulonglong2*)(We + c0);
    ulonglong2 weB = *(const ulonglong2*)(We + c0 + 4);
    ulonglong2 atA = *(const ulonglong2*)(att + c0);
    ulonglong2 atB = *(const ulonglong2*)(att + c0 + 4);
    u64 we2[4] = {weA.x, weA.y, weB.x, weB.y};
    u64 at2[4] = {atA.x, atA.y, atB.x, atB.y};
    const u64 c06 = pk2(0.6f, 0.6f), c04 = pk2(0.4f, 0.4f);

    u64 accp[4] = {0ull, 0ull, 0ull, 0ull};
    float dsum = 0.f, easum = 0.f;

    // uniform loop bound across the warp (both nodes)
    int cnto = __shfl_xor_sync(0xffffffffu, cnt, 16);
    int maxc = max(cnt, cnto);

    const size_t sbase = (size_t)n * SLOT;
    int i = 0;
    for (; i + 1 < maxc; i += 2) {
        ulonglong2 pp = *(const ulonglong2*)(d_sadj + sbase + i);
        int   src1 = (int)(u32)pp.x; float ea1 = __uint_as_float((u32)(pp.x >> 32));
        int   src2 = (int)(u32)pp.y; float ea2 = __uint_as_float((u32)(pp.y >> 32));
        const ulonglong2* p1 = (const ulonglong2*)(d_xl2 + (size_t)src1 * 128 + c0);
        const ulonglong2* p2 = (const ulonglong2*)(d_xl2 + (size_t)src2 * 128 + c0);
        ulonglong2 l1a = p1[0], l1b = p1[1];
        ulonglong2 l2a = p2[0], l2b = p2[1];
        u64 l1[4] = {l1a.x, l1a.y, l1b.x, l1b.y};
        u64 l2[4] = {l2a.x, l2a.y, l2b.x, l2b.y};
        u64 ev1 = pk2(ea1, ea1), ev2 = pk2(ea2, ea2);
        easum += (i < cnt ? ea1 : 0.f) + (i + 1 < cnt ? ea2 : 0.f);
        u64 lg1 = 0ull, lg2 = 0ull;
#pragma unroll
        for (int p = 0; p < 4; p++) {
            lg1 = gat2(l1[p], xr2v[p], we2[p], at2[p], ev1, c06, c04, lg1);
            lg2 = gat2(l2[p], xr2v[p], we2[p], at2[p], ev2, c06, c04, lg2);
        }
        float lo1, hi1, lo2, hi2;
        upk2(lg1, lo1, hi1); upk2(lg2, lo2, hi2);
        float a1 = lo1 + hi1, a2 = lo2 + hi2;
        a1 += __shfl_xor_sync(0xffffffffu, a1, 1);
        a2 += __shfl_xor_sync(0xffffffffu, a2, 1);
        a1 += __shfl_xor_sync(0xffffffffu, a1, 2);
        a2 += __shfl_xor_sync(0xffffffffu, a2, 2);
        a1 += __shfl_xor_sync(0xffffffffu, a1, 4);
        a2 += __shfl_xor_sync(0xffffffffu, a2, 4);
        a1 += __shfl_xor_sync(0xffffffffu, a1, 8);
        a2 += __shfl_xor_sync(0xffffffffu, a2, 8);
        // mask edges beyond this node's own count (exp underflows to 0)
        if (i >= cnt)     a1 = -1e30f;
        if (i + 1 >= cnt) a2 = -1e30f;
        float e1 = sexp(a1);
        float e2 = sexp(a2);
        dsum += e1 + e2;
        u64 e12 = pk2(e1, e1), e22 = pk2(e2, e2);
#pragma unroll
        for (int p = 0; p < 4; p++)
            accp[p] = fma2(e22, l2[p], fma2(e12, l1[p], accp[p]));
    }
    if (i < maxc) {
        u64 p = d_sadj[sbase + i];
        int src1 = (int)(u32)p; float ea1 = __uint_as_float((u32)(p >> 32));
        const ulonglong2* p1 = (const ulonglong2*)(d_xl2 + (size_t)src1 * 128 + c0);
        ulonglong2 l1a = p1[0], l1b = p1[1];
        u64 l1[4] = {l1a.x, l1a.y, l1b.x, l1b.y};
        u64 ev1 = pk2(ea1, ea1);
        easum += (i < cnt ? ea1 : 0.f);
        u64 lg1 = 0ull;
#pragma unroll
        for (int q = 0; q < 4; q++) lg1 = gat2(l1[q], xr2v[q], we2[q], at2[q], ev1, c06, c04, lg1);
        float lo1, hi1; upk2(lg1, lo1, hi1);
        float a1 = lo1 + hi1;
        a1 += __shfl_xor_sync(0xffffffffu, a1, 1);
        a1 += __shfl_xor_sync(0xffffffffu, a1, 2);
        a1 += __shfl_xor_sync(0xffffffffu, a1, 4);
        a1 += __shfl_xor_sync(0xffffffffu, a1, 8);
        if (i >= cnt) a1 = -1e30f;
        float e1 = sexp(a1);
        dsum += e1;
        u64 e12 = pk2(e1, e1);
#pragma unroll
        for (int q = 0; q < 4; q++)
            accp[q] = fma2(e12, l1[q], accp[q]);
    }

    // ---- self-loop last ----
    {
        float loopv = easum / fmaxf((float)cnt, 1.f);
        const ulonglong2* psl = (const ulonglong2*)(d_xl2 + (size_t)n * 128 + c0);
        ulonglong2 s0 = psl[0], s1 = psl[1];
        u64 sl[4] = {s0.x, s0.y, s1.x, s1.y};
        u64 ev = pk2(loopv, loopv);
        u64 lg = 0ull;
#pragma unroll
        for (int p = 0; p < 4; p++) lg = gat2(sl[p], xr2v[p], we2[p], at2[p], ev, c06, c04, lg);
        float lo, hi; upk2(lg, lo, hi);
        float a = lo + hi;
        a += __shfl_xor_sync(0xffffffffu, a, 1);
        a += __shfl_xor_sync(0xffffffffu, a, 2);
        a += __shfl_xor_sync(0xffffffffu, a, 4);
        a += __shfl_xor_sync(0xffffffffu, a, 8);
        float e0 = sexp(a);
        dsum += e0;
        u64 e02 = pk2(e0, e0);
#pragma unroll
        for (int p = 0; p < 4; p++) accp[p] = fma2(e02, sl[p], accp[p]);
    }

    float inv = 1.f / (dsum + 1e-16f);
    float o[8];
#pragma unroll
    for (int p = 0; p < 4; p++) upk2(accp[p], o[2 * p], o[2 * p + 1]);
    float4 bA = __ldg((const float4*)(b2 + c0));
    float4 bB = __ldg((const float4*)(b2 + c0 + 4));
    o[0] = o[0] * inv + bA.x; o[1] = o[1] * inv + bA.y;
    o[2] = o[2] * inv + bA.z; o[3] = o[3] * inv + bA.w;
    o[4] = o[4] * inv + bB.x; o[5] = o[5] * inv + bB.y;
    o[6] = o[6] * inv + bB.z; o[7] = o[7] * inv + bB.w;

    // LayerNorm(128) across the 16-lane half
    float s = 0.f, s2 = 0.f;
#pragma unroll
    for (int j = 0; j < 8; j++) { s += o[j]; s2 += o[j] * o[j]; }
#pragma unroll
    for (int d = 8; d >= 1; d >>= 1) {
        s  += __shfl_xor_sync(0xffffffffu, s, d);
        s2 += __shfl_xor_sync(0xffffffffu, s2, d);
    }
    float mu = s * (1.f / 128.f);
    float var = s2 * (1.f / 128.f) - mu * mu;
    float rstd = rsqrtf(var + 1e-5f);
    float4 gA = __ldg((const float4*)(g2 + c0));
    float4 gB = __ldg((const float4*)(g2 + c0 + 4));
    float4 tA = __ldg((const float4*)(beta2 + c0));
    float4 tB = __ldg((const float4*)(beta2 + c0 + 4));
    float y[8];
    y[0] = (o[0]-mu)*rstd*gA.x + tA.x; y[1] = (o[1]-mu)*rstd*gA.y + tA.y;
    y[2] = (o[2]-mu)*rstd*gA.z + tA.z; y[3] = (o[3]-mu)*rstd*gA.w + tA.w;
    y[4] = (o[4]-mu)*rstd*gB.x + tB.x; y[5] = (o[5]-mu)*rstd*gB.y + tB.y;
    y[6] = (o[6]-mu)*rstd*gB.z + tB.z; y[7] = (o[7]-mu)*rstd*gB.w + tB.w;
#pragma unroll
    for (int j = 0; j < 8; j++) y[j] = (y[j] > 0.f) ? y[j] : (__expf(y[j]) - 1.f);
    float4* ph = (float4*)(d_h2 + (size_t)n * 128 + c0);
    ph[0] = make_float4(y[0], y[1], y[2], y[3]);
    ph[1] = make_float4(y[4], y[5], y[6], y[7]);
}

// pooling: block of 128 threads handles 32 consecutive nodes (batch is sorted)
__global__ void k_pool(const int* __restrict__ batch) {
    __shared__ int s_b[32];
    int n0 = blockIdx.x * 32;
    int tid = threadIdx.x;
    if (tid < 32) {
        int n = n0 + tid;
        s_b[tid] = (n < NN) ? batch[n] : -1;
    }
    __syncthreads();
    int c = tid;
    float acc = 0.f;
    int cur = s_b[0];
    for (int j = 0; j < 32; j++) {
        int n = n0 + j;
        if (n >= NN) break;
        int g = s_b[j];
        if (g != cur) {
            atomicAdd(&d_pool[cur * 128 + c], acc);
            acc = 0.f;
            cur = g;
        }
        acc += d_h2[(size_t)n * 128 + c];
    }
    atomicAdd(&d_pool[cur * 128 + c], acc);
    if (tid == 0) {
        int cg = s_b[0];
        float ct = 0.f;
        for (int j = 0; j < 32; j++) {
            int n = n0 + j;
            if (n >= NN) break;
            int g = s_b[j];
            if (g != cg) { atomicAdd(&d_cnt[cg], ct); ct = 0.f; cg = g; }
            ct += 1.f;
        }
        atomicAdd(&d_cnt[cg], ct);
    }
}

__global__ void k_pooldiv(float* __restrict__ out) {
    int g = blockIdx.x, c = threadIdx.x;
    out[g * 128 + c] = d_pool[g * 128 + c] / fmaxf(d_cnt[g], 1.f);
    d_pool[g * 128 + c] = 0.f;      // reset for next replay
    if (c == 0) d_cnt[g] = 0.f;
}

// ---------------------------------------------------------------------------
extern "C" void kernel_launch(void* const* d_in, const int* in_sizes, int n_in,
                              void* d_out, int out_size) {
    const float* x     = (const float*)d_in[0];
    const int*   ei    = (const int*)  d_in[1];
    const float* ea    = (const float*)d_in[2];
    const int*   batch = (const int*)  d_in[3];
    const float* Wl1   = (const float*)d_in[4];
    const float* Wr1   = (const float*)d_in[5];
    const float* We1   = (const float*)d_in[6];
    const float* att1  = (const float*)d_in[7];
    const float* b1    = (const float*)d_in[8];
    const float* g1    = (const float*)d_in[9];
    const float* beta1 = (const float*)d_in[10];
    const float* Wl2   = (const float*)d_in[11];
    const float* Wr2   = (const float*)d_in[12];
    const float* We2   = (const float*)d_in[13];
    const float* att2  = (const float*)d_in[14];
    const float* b2    = (const float*)d_in[15];
    const float* g2    = (const float*)d_in[16];
    const float* beta2 = (const float*)d_in[17];
    float* out = (float*)d_out;

    k_gfill<<<GEMM1_BLKS + FILL_BLKS, 256>>>(x, Wl1, ei, ea);         // #1
    k_fagg1<<<(NN + 7) / 8, 256>>>(x, Wr1, We1, att1, b1, g1, beta1); // #2
    k_gemm2<<<(NN + 127) / 128, 512>>>(Wl2, Wr2);                     // #3
    k_fagg2<<<NN / 16, 256>>>(We2, att2, b2, g2, beta2);              // #4 (profiled)
    k_pool<<<(NN + 31) / 32, 128>>>(batch);                           // #5
    k_pooldiv<<<NG, 128>>>(out);                                      // #6
}

// round 14
// speedup vs baseline: 1.1166x; 1.1166x over previous
#include <cuda_runtime.h>
#include <math.h>

#define NN 50000
#define NE 800000
#define NG 64
#define SLOT 96

typedef unsigned long long u64;
typedef unsigned int u32;

// ------------------- scratch (device globals; zero-initialized at load) ----
__device__ float d_xl1[NN * 256];
__device__ float d_h1 [NN * 256];
__device__ float d_xl2[NN * 128];
__device__ float d_xr2[NN * 128];
__device__ float d_h2 [NN * 128];
__device__ int   d_cursor[NN];
__device__ u64   d_sadj[(size_t)NN * SLOT];   // packed (ea:f32 hi, src:i32 lo)
__device__ float d_pool[NG * 128];
__device__ float d_cnt[NG];

// ---------------- packed f32x2 helpers --------------------------------------
__device__ __forceinline__ u64 pk2(float lo, float hi) {
    u64 r; asm("mov.b64 %0, {%1,%2};" : "=l"(r) : "f"(lo), "f"(hi)); return r;
}
__device__ __forceinline__ void upk2(u64 v, float& lo, float& hi) {
    asm("mov.b64 {%0,%1}, %2;" : "=f"(lo), "=f"(hi) : "l"(v));
}
__device__ __forceinline__ u64 add2(u64 a, u64 b) {
    u64 d; asm("add.rn.f32x2 %0, %1, %2;" : "=l"(d) : "l"(a), "l"(b)); return d;
}
__device__ __forceinline__ u64 mul2(u64 a, u64 b) {
    u64 d; asm("mul.rn.f32x2 %0, %1, %2;" : "=l"(d) : "l"(a), "l"(b)); return d;
}
__device__ __forceinline__ u64 fma2(u64 a, u64 b, u64 c) {
    u64 d; asm("fma.rn.f32x2 %0, %1, %2, %3;" : "=l"(d) : "l"(a), "l"(b), "l"(c)); return d;
}
#define ABS2 0x7FFFFFFF7FFFFFFFull

// packed GATv2 logit contribution: t = leaky(l + xr + eav*we); lg += t*at
__device__ __forceinline__ u64 gat2(u64 l, u64 xr, u64 we, u64 at, u64 eav2,
                                    u64 c06, u64 c04, u64 lg) {
    u64 t = add2(l, xr);
    t = fma2(eav2, we, t);
    u64 ab = t & ABS2;
    t = fma2(c04, ab, mul2(t, c06));    // = m>0 ? m : 0.2m
    return fma2(t, at, lg);
}

// safe exp: logits here are O(10); clamp is a never-hit overflow guard
__device__ __forceinline__ float sexp(float a) { return __expf(fminf(a, 80.f)); }

// ---------------------------------------------------------------------------
// FUSED: gemm1 (xl1 = x @ Wl1) + adjacency fill, split by block role
#define GEMM1_BLKS (NN / 4)           // 12500
#define FILL_BLKS  ((NE + 255) / 256) // 3125
__global__ void k_gfill(const float* __restrict__ x, const float* __restrict__ Wl,
                        const int* __restrict__ ei, const float* __restrict__ ea) {
    int tid = threadIdx.x;
    if (blockIdx.x < GEMM1_BLKS) {
        __shared__ float sx[32];
        int n0 = blockIdx.x * 4;
        if (tid < 32) sx[tid] = x[n0 * 8 + tid];
        __syncthreads();
        float w[8];
#pragma unroll
        for (int k = 0; k < 8; k++) w[k] = Wl[k * 256 + tid];
#pragma unroll
        for (int q = 0; q < 4; q++) {
            float a = 0.f;
#pragma unroll
            for (int k = 0; k < 8; k++) a += sx[q * 8 + k] * w[k];
            d_xl1[(size_t)(n0 + q) * 256 + tid] = a;
        }
    } else {
        int e = (blockIdx.x - GEMM1_BLKS) * 256 + tid;
        if (e < NE) {
            int dst = ei[NE + e];
            int src = ei[e];
            float v = ea[e];
            int p = atomicAdd(&d_cursor[dst], 1);
            if (p < SLOT)
                d_sadj[(size_t)dst * SLOT + p] =
                    ((u64)__float_as_uint(v) << 32) | (u32)src;
        }
    }
}

// ======== layer-1 FUSED, warp per node, unnormalized-exp softmax ============
// Lane owns channels [lane*8, lane*8+8); head = lane>>3 (8-lane segments).
// Self-loop processed LAST (order-free with unnormalized exp); loopv computed
// from easum accumulated in the edge loop (eav is warp-uniform).
__global__ __launch_bounds__(256, 4) void
k_fagg1(const float* __restrict__ x,
        const float* __restrict__ Wr, const float* __restrict__ We,
        const float* __restrict__ att,
        const float* __restrict__ b1, const float* __restrict__ g1,
        const float* __restrict__ beta1) {
    int wid = threadIdx.x >> 5, lane = threadIdx.x & 31;
    int n = blockIdx.x * 8 + wid;

    int cnt = d_cursor[n];
    if (cnt > SLOT) cnt = SLOT;

    int c0 = lane * 8;

    // xr row: x[n] (8) @ Wr (8x256), this lane's 8 channels (scalar, then pack)
    float xv = (lane < 8) ? x[n * 8 + lane] : 0.f;
    float xr[8];
#pragma unroll
    for (int j = 0; j < 8; j++) xr[j] = 0.f;
#pragma unroll
    for (int k = 0; k < 8; k++) {
        float xk = __shfl_sync(0xffffffffu, xv, k);
        float4 wA = __ldg((const float4*)(Wr + k * 256 + c0));
        float4 wB = __ldg((const float4*)(Wr + k * 256 + c0 + 4));
        xr[0] += xk * wA.x; xr[1] += xk * wA.y; xr[2] += xk * wA.z; xr[3] += xk * wA.w;
        xr[4] += xk * wB.x; xr[5] += xk * wB.y; xr[6] += xk * wB.z; xr[7] += xk * wB.w;
    }
    u64 xr2[4];
#pragma unroll
    for (int p = 0; p < 4; p++) xr2[p] = pk2(xr[2 * p], xr[2 * p + 1]);

    ulonglong2 weL = *(const ulonglong2*)(We + c0);
    ulonglong2 weH = *(const ulonglong2*)(We + c0 + 4);
    ulonglong2 atL = *(const ulonglong2*)(att + c0);
    ulonglong2 atH = *(const ulonglong2*)(att + c0 + 4);
    u64 we2[4] = {weL.x, weL.y, weH.x, weH.y};
    u64 at2[4] = {atL.x, atL.y, atH.x, atH.y};
    const u64 c06 = pk2(0.6f, 0.6f), c04 = pk2(0.4f, 0.4f);

    u64 accp[4] = {0ull, 0ull, 0ull, 0ull};
    float dsum = 0.f, easum = 0.f;

    const size_t sbase = (size_t)n * SLOT;
    int i = 0;
    // ---- pairs of edges (iterations fully independent) ----
    for (; i + 1 < cnt; i += 2) {
        ulonglong2 pp = *(const ulonglong2*)(d_sadj + sbase + i);
        int   src1 = (int)(u32)pp.x; float ea1 = __uint_as_float((u32)(pp.x >> 32));
        int   src2 = (int)(u32)pp.y; float ea2 = __uint_as_float((u32)(pp.y >> 32));
        const ulonglong2* p1 = (const ulonglong2*)(d_xl1 + (size_t)src1 * 256 + c0);
        const ulonglong2* p2 = (const ulonglong2*)(d_xl1 + (size_t)src2 * 256 + c0);
        ulonglong2 l1a = p1[0], l1b = p1[1];
        ulonglong2 l2a = p2[0], l2b = p2[1];
        u64 l1[4] = {l1a.x, l1a.y, l1b.x, l1b.y};
        u64 l2[4] = {l2a.x, l2a.y, l2b.x, l2b.y};
        u64 ev1 = pk2(ea1, ea1), ev2 = pk2(ea2, ea2);
        easum += ea1 + ea2;
        u64 lg1 = 0ull, lg2 = 0ull;
#pragma unroll
        for (int p = 0; p < 4; p++) {
            lg1 = gat2(l1[p], xr2[p], we2[p], at2[p], ev1, c06, c04, lg1);
            lg2 = gat2(l2[p], xr2[p], we2[p], at2[p], ev2, c06, c04, lg2);
        }
        float lo1, hi1, lo2, hi2;
        upk2(lg1, lo1, hi1); upk2(lg2, lo2, hi2);
        float a1 = lo1 + hi1, a2 = lo2 + hi2;
        a1 += __shfl_xor_sync(0xffffffffu, a1, 1);
        a2 += __shfl_xor_sync(0xffffffffu, a2, 1);
        a1 += __shfl_xor_sync(0xffffffffu, a1, 2);
        a2 += __shfl_xor_sync(0xffffffffu, a2, 2);
        a1 += __shfl_xor_sync(0xffffffffu, a1, 4);
        a2 += __shfl_xor_sync(0xffffffffu, a2, 4);
        float e1 = sexp(a1);
        float e2 = sexp(a2);
        dsum += e1 + e2;
        u64 e12 = pk2(e1, e1), e22 = pk2(e2, e2);
#pragma unroll
        for (int p = 0; p < 4; p++)
            accp[p] = fma2(e22, l2[p], fma2(e12, l1[p], accp[p]));
    }
    // ---- odd tail edge ----
    if (i < cnt) {
        u64 p = d_sadj[sbase + i];
        int src1 = (int)(u32)p; float ea1 = __uint_as_float((u32)(p >> 32));
        const ulonglong2* p1 = (const ulonglong2*)(d_xl1 + (size_t)src1 * 256 + c0);
        ulonglong2 l1a = p1[0], l1b = p1[1];
        u64 l1[4] = {l1a.x, l1a.y, l1b.x, l1b.y};
        u64 ev1 = pk2(ea1, ea1);
        easum += ea1;
        u64 lg1 = 0ull;
#pragma unroll
        for (int q = 0; q < 4; q++) lg1 = gat2(l1[q], xr2[q], we2[q], at2[q], ev1, c06, c04, lg1);
        float lo1, hi1; upk2(lg1, lo1, hi1);
        float a1 = lo1 + hi1;
        a1 += __shfl_xor_sync(0xffffffffu, a1, 1);
        a1 += __shfl_xor_sync(0xffffffffu, a1, 2);
        a1 += __shfl_xor_sync(0xffffffffu, a1, 4);
        float e1 = sexp(a1);
        dsum += e1;
        u64 e12 = pk2(e1, e1);
#pragma unroll
        for (int q = 0; q < 4; q++)
            accp[q] = fma2(e12, l1[q], accp[q]);
    }

    // ---- self-loop last ----
    {
        float loopv = easum / fmaxf((float)cnt, 1.f);
        const ulonglong2* ps = (const ulonglong2*)(d_xl1 + (size_t)n * 256 + c0);
        ulonglong2 s0 = ps[0], s1 = ps[1];
        u64 sl[4] = {s0.x, s0.y, s1.x, s1.y};
        u64 eav2 = pk2(loopv, loopv);
        u64 lg = 0ull;
#pragma unroll
        for (int p = 0; p < 4; p++) lg = gat2(sl[p], xr2[p], we2[p], at2[p], eav2, c06, c04, lg);
        float lo, hi; upk2(lg, lo, hi);
        float a = lo + hi;
        a += __shfl_xor_sync(0xffffffffu, a, 1);
        a += __shfl_xor_sync(0xffffffffu, a, 2);
        a += __shfl_xor_sync(0xffffffffu, a, 4);
        float e0 = sexp(a);
        dsum += e0;
        u64 e02 = pk2(e0, e0);
#pragma unroll
        for (int p = 0; p < 4; p++) accp[p] = fma2(e02, sl[p], accp[p]);
    }

    float inv = 1.f / (dsum + 1e-16f);
    float o[8];
#pragma unroll
    for (int p = 0; p < 4; p++) upk2(accp[p], o[2 * p], o[2 * p + 1]);
    float4 bA = __ldg((const float4*)(b1 + c0));
    float4 bB = __ldg((const float4*)(b1 + c0 + 4));
    o[0] = o[0] * inv + bA.x; o[1] = o[1] * inv + bA.y;
    o[2] = o[2] * inv + bA.z; o[3] = o[3] * inv + bA.w;
    o[4] = o[4] * inv + bB.x; o[5] = o[5] * inv + bB.y;
    o[6] = o[6] * inv + bB.z; o[7] = o[7] * inv + bB.w;

    // LayerNorm(256) across the warp
    float s = 0.f, s2 = 0.f;
#pragma unroll
    for (int j = 0; j < 8; j++) { s += o[j]; s2 += o[j] * o[j]; }
#pragma unroll
    for (int d = 16; d >= 1; d >>= 1) {
        s  += __shfl_xor_sync(0xffffffffu, s, d);
        s2 += __shfl_xor_sync(0xffffffffu, s2, d);
    }
    float mu = s * (1.f / 256.f);
    float var = s2 * (1.f / 256.f) - mu * mu;
    float rstd = rsqrtf(var + 1e-5f);
    float4 gA = __ldg((const float4*)(g1 + c0));
    float4 gB = __ldg((const float4*)(g1 + c0 + 4));
    float4 tA = __ldg((const float4*)(beta1 + c0));
    float4 tB = __ldg((const float4*)(beta1 + c0 + 4));
    float y[8];
    y[0] = (o[0]-mu)*rstd*gA.x + tA.x; y[1] = (o[1]-mu)*rstd*gA.y + tA.y;
    y[2] = (o[2]-mu)*rstd*gA.z + tA.z; y[3] = (o[3]-mu)*rstd*gA.w + tA.w;
    y[4] = (o[4]-mu)*rstd*gB.x + tB.x; y[5] = (o[5]-mu)*rstd*gB.y + tB.y;
    y[6] = (o[6]-mu)*rstd*gB.z + tB.z; y[7] = (o[7]-mu)*rstd*gB.w + tB.w;
#pragma unroll
    for (int j = 0; j < 8; j++) y[j] = (y[j] > 0.f) ? y[j] : (__expf(y[j]) - 1.f);
    float4* ph = (float4*)(d_h1 + (size_t)n * 256 + c0);
    ph[0] = make_float4(y[0], y[1], y[2], y[3]);
    ph[1] = make_float4(y[4], y[5], y[6], y[7]);
}

// ======== GEMM2 via tf32 mma.sync, SMEM-staged + reg prefetch ===============
__device__ __forceinline__ u32 f2tf(float f) {
    u32 u;
    asm("cvt.rna.tf32.f32 %0, %1;" : "=r"(u) : "f"(f));
    return u;
}
__device__ __forceinline__ void mma_tf32(float* d, const u32* a, u32 b0, u32 b1) {
    asm("mma.sync.aligned.m16n8k8.row.col.f32.tf32.tf32.f32 "
        "{%0,%1,%2,%3}, {%4,%5,%6,%7}, {%8,%9}, {%0,%1,%2,%3};"
        : "+f"(d[0]), "+f"(d[1]), "+f"(d[2]), "+f"(d[3])
        : "r"(a[0]), "r"(a[1]), "r"(a[2]), "r"(a[3]), "r"(b0), "r"(b1));
}

#define GK 16
__global__ __launch_bounds__(512) void
k_gemm2(const float* __restrict__ Wl, const float* __restrict__ Wr) {
    __shared__ u32 sA[128][20];
    __shared__ u32 sB[GK][264];
    int tid = threadIdx.x;
    int w = tid >> 5, lane = tid & 31;
    int gid = lane >> 2, tig = lane & 3;
    int mgrp = w >> 2, ngrp = w & 3;
    int row0 = blockIdx.x * 128;
    int wm0 = mgrp * 32;
    int wn0 = ngrp * 64;

    float d[2][8][4];
#pragma unroll
    for (int mt = 0; mt < 2; mt++)
#pragma unroll
        for (int nt = 0; nt < 8; nt++)
#pragma unroll
            for (int q = 0; q < 4; q++) d[mt][nt][q] = 0.f;

    int ar = tid >> 2, akq = tid & 3;
    int gr = min(row0 + ar, NN - 1);
    const float4* aptr = (const float4*)(d_h1 + (size_t)gr * 256 + akq * 4);
    int kr0 = tid >> 6,         cq0 = tid & 63;
    int kr1 = (tid + 512) >> 6, cq1 = (tid + 512) & 63;
    const float* bsrc0 = (cq0 < 32) ? (Wl + kr0 * 128 + cq0 * 4)
                                    : (Wr + kr0 * 128 + (cq0 - 32) * 4);
    const float* bsrc1 = (cq1 < 32) ? (Wl + kr1 * 128 + cq1 * 4)
                                    : (Wr + kr1 * 128 + (cq1 - 32) * 4);

    float4 va = aptr[0];
    float4 vb0 = *(const float4*)bsrc0;
    float4 vb1 = *(const float4*)bsrc1;

    for (int k0 = 0; k0 < 256; k0 += GK) {
        sA[ar][akq * 4 + 0] = f2tf(va.x);
        sA[ar][akq * 4 + 1] = f2tf(va.y);
        sA[ar][akq * 4 + 2] = f2tf(va.z);
        sA[ar][akq * 4 + 3] = f2tf(va.w);
        sB[kr0][cq0 * 4 + 0] = f2tf(vb0.x);
        sB[kr0][cq0 * 4 + 1] = f2tf(vb0.y);
        sB[kr0][cq0 * 4 + 2] = f2tf(vb0.z);
        sB[kr0][cq0 * 4 + 3] = f2tf(vb0.w);
        sB[kr1][cq1 * 4 + 0] = f2tf(vb1.x);
        sB[kr1][cq1 * 4 + 1] = f2tf(vb1.y);
        sB[kr1][cq1 * 4 + 2] = f2tf(vb1.z);
        sB[kr1][cq1 * 4 + 3] = f2tf(vb1.w);
        __syncthreads();
        if (k0 + GK < 256) {
            va  = aptr[(k0 + GK) >> 2];
            vb0 = *(const float4*)(bsrc0 + (size_t)(k0 + GK) * 128);
            vb1 = *(const float4*)(bsrc1 + (size_t)(k0 + GK) * 128);
        }
#pragma unroll
        for (int kk = 0; kk < GK; kk += 8) {
            u32 a[2][4];
            a[0][0] = sA[wm0 + gid][kk + tig];
            a[0][1] = sA[wm0 + gid + 8][kk + tig];
            a[0][2] = sA[wm0 + gid][kk + tig + 4];
            a[0][3] = sA[wm0 + gid + 8][kk + tig + 4];
            a[1][0] = sA[wm0 + 16 + gid][kk + tig];
            a[1][1] = sA[wm0 + 24 + gid][kk + tig];
            a[1][2] = sA[wm0 + 16 + gid][kk + tig + 4];
            a[1][3] = sA[wm0 + 24 + gid][kk + tig + 4];
#pragma unroll
            for (int nt = 0; nt < 8; nt++) {
                int c = wn0 + nt * 8 + gid;
                u32 b0 = sB[kk + tig][c];
                u32 b1 = sB[kk + tig + 4][c];
                mma_tf32(d[0][nt], a[0], b0, b1);
                mma_tf32(d[1][nt], a[1], b0, b1);
            }
        }
        __syncthreads();
    }

    float* OUT = (wn0 < 128) ? d_xl2 : d_xr2;
#pragma unroll
    for (int mt = 0; mt < 2; mt++) {
        int rA = row0 + wm0 + mt * 16 + gid;
        int rB = rA + 8;
#pragma unroll
        for (int nt = 0; nt < 8; nt++) {
            int cc = (wn0 + nt * 8 + 2 * tig) & 127;
            if (rA < NN)
                *(float2*)(OUT + (size_t)rA * 128 + cc) = make_float2(d[mt][nt][0], d[mt][nt][1]);
            if (rB < NN)
                *(float2*)(OUT + (size_t)rB * 128 + cc) = make_float2(d[mt][nt][2], d[mt][nt][3]);
        }
    }
}

// ======== layer-2 FUSED: 2 nodes per warp, unnormalized-exp softmax =========
// Lane owns 8 channels: c0 = (lane&15)*8 of node (wid*2 + lane>>4).
// launch_bounds(256, 4): validated optimum (5 caused reg spills, R13).
__global__ __launch_bounds__(256, 4) void
k_fagg2(const float* __restrict__ We, const float* __restrict__ att,
        const float* __restrict__ b2, const float* __restrict__ g2,
        const float* __restrict__ beta2) {
    int wid = threadIdx.x >> 5, lane = threadIdx.x & 31;
    int half = lane >> 4, lane16 = lane & 15;
    int n = blockIdx.x * 16 + wid * 2 + half;

    int cnt = d_cursor[n];
    if (cnt > SLOT) cnt = SLOT;
    if (lane16 == 0) d_cursor[n] = 0;   // reset for next replay

    int c0 = lane16 * 8;
    const ulonglong2* pxr = (const ulonglong2*)(d_xr2 + (size_t)n * 128 + c0);
    ulonglong2 xrA = pxr[0], xrB = pxr[1];
    u64 xr2v[4] = {xrA.x, xrA.y, xrB.x, xrB.y};
    ulonglong2 weA = *(const ulonglong2*)(We + c0);
    ulonglong2 weB = *(const ulonglong2*)(We + c0 + 4);
    ulonglong2 atA = *(const ulonglong2*)(att + c0);
    ulonglong2 atB = *(const ulonglong2*)(att + c0 + 4);
    u64 we2[4] = {weA.x, weA.y, weB.x, weB.y};
    u64 at2[4] = {atA.x, atA.y, atB.x, atB.y};
    const u64 c06 = pk2(0.6f, 0.6f), c04 = pk2(0.4f, 0.4f);

    u64 accp[4] = {0ull, 0ull, 0ull, 0ull};
    float dsum = 0.f, easum = 0.f;

    // uniform loop bound across the warp (both nodes)
    int cnto = __shfl_xor_sync(0xffffffffu, cnt, 16);
    int maxc = max(cnt, cnto);

    const size_t sbase = (size_t)n * SLOT;
    int i = 0;
    for (; i + 1 < maxc; i += 2) {
        ulonglong2 pp = *(const ulonglong2*)(d_sadj + sbase + i);
        int   src1 = (int)(u32)pp.x; float ea1 = __uint_as_float((u32)(pp.x >> 32));
        int   src2 = (int)(u32)pp.y; float ea2 = __uint_as_float((u32)(pp.y >> 32));
        const ulonglong2* p1 = (const ulonglong2*)(d_xl2 + (size_t)src1 * 128 + c0);
        const ulonglong2* p2 = (const ulonglong2*)(d_xl2 + (size_t)src2 * 128 + c0);
        ulonglong2 l1a = p1[0], l1b = p1[1];
        ulonglong2 l2a = p2[0], l2b = p2[1];
        u64 l1[4] = {l1a.x, l1a.y, l1b.x, l1b.y};
        u64 l2[4] = {l2a.x, l2a.y, l2b.x, l2b.y};
        u64 ev1 = pk2(ea1, ea1), ev2 = pk2(ea2, ea2);
        easum += (i < cnt ? ea1 : 0.f) + (i + 1 < cnt ? ea2 : 0.f);
        u64 lg1 = 0ull, lg2 = 0ull;
#pragma unroll
        for (int p = 0; p < 4; p++) {
            lg1 = gat2(l1[p], xr2v[p], we2[p], at2[p], ev1, c06, c04, lg1);
            lg2 = gat2(l2[p], xr2v[p], we2[p], at2[p], ev2, c06, c04, lg2);
        }
        float lo1, hi1, lo2, hi2;
        upk2(lg1, lo1, hi1); upk2(lg2, lo2, hi2);
        float a1 = lo1 + hi1, a2 = lo2 + hi2;
        a1 += __shfl_xor_sync(0xffffffffu, a1, 1);
        a2 += __shfl_xor_sync(0xffffffffu, a2, 1);
        a1 += __shfl_xor_sync(0xffffffffu, a1, 2);
        a2 += __shfl_xor_sync(0xffffffffu, a2, 2);
        a1 += __shfl_xor_sync(0xffffffffu, a1, 4);
        a2 += __shfl_xor_sync(0xffffffffu, a2, 4);
        a1 += __shfl_xor_sync(0xffffffffu, a1, 8);
        a2 += __shfl_xor_sync(0xffffffffu, a2, 8);
        // mask edges beyond this node's own count (exp underflows to 0)
        if (i >= cnt)     a1 = -1e30f;
        if (i + 1 >= cnt) a2 = -1e30f;
        float e1 = sexp(a1);
        float e2 = sexp(a2);
        dsum += e1 + e2;
        u64 e12 = pk2(e1, e1), e22 = pk2(e2, e2);
#pragma unroll
        for (int p = 0; p < 4; p++)
            accp[p] = fma2(e22, l2[p], fma2(e12, l1[p], accp[p]));
    }
    if (i < maxc) {
        u64 p = d_sadj[sbase + i];
        int src1 = (int)(u32)p; float ea1 = __uint_as_float((u32)(p >> 32));
        const ulonglong2* p1 = (const ulonglong2*)(d_xl2 + (size_t)src1 * 128 + c0);
        ulonglong2 l1a = p1[0], l1b = p1[1];
        u64 l1[4] = {l1a.x, l1a.y, l1b.x, l1b.y};
        u64 ev1 = pk2(ea1, ea1);
        easum += (i < cnt ? ea1 : 0.f);
        u64 lg1 = 0ull;
#pragma unroll
        for (int q = 0; q < 4; q++) lg1 = gat2(l1[q], xr2v[q], we2[q], at2[q], ev1, c06, c04, lg1);
        float lo1, hi1; upk2(lg1, lo1, hi1);
        float a1 = lo1 + hi1;
        a1 += __shfl_xor_sync(0xffffffffu, a1, 1);
        a1 += __shfl_xor_sync(0xffffffffu, a1, 2);
        a1 += __shfl_xor_sync(0xffffffffu, a1, 4);
        a1 += __shfl_xor_sync(0xffffffffu, a1, 8);
        if (i >= cnt) a1 = -1e30f;
        float e1 = sexp(a1);
        dsum += e1;
        u64 e12 = pk2(e1, e1);
#pragma unroll
        for (int q = 0; q < 4; q++)
            accp[q] = fma2(e12, l1[q], accp[q]);
    }

    // ---- self-loop last ----
    {
        float loopv = easum / fmaxf((float)cnt, 1.f);
        const ulonglong2* psl = (const ulonglong2*)(d_xl2 + (size_t)n * 128 + c0);
        ulonglong2 s0 = psl[0], s1 = psl[1];
        u64 sl[4] = {s0.x, s0.y, s1.x, s1.y};
        u64 ev = pk2(loopv, loopv);
        u64 lg = 0ull;
#pragma unroll
        for (int p = 0; p < 4; p++) lg = gat2(sl[p], xr2v[p], we2[p], at2[p], ev, c06, c04, lg);
        float lo, hi; upk2(lg, lo, hi);
        float a = lo + hi;
        a += __shfl_xor_sync(0xffffffffu, a, 1);
        a += __shfl_xor_sync(0xffffffffu, a, 2);
        a += __shfl_xor_sync(0xffffffffu, a, 4);
        a += __shfl_xor_sync(0xffffffffu, a, 8);
        float e0 = sexp(a);
        dsum += e0;
        u64 e02 = pk2(e0, e0);
#pragma unroll
        for (int p = 0; p < 4; p++) accp[p] = fma2(e02, sl[p], accp[p]);
    }

    float inv = 1.f / (dsum + 1e-16f);
    float o[8];
#pragma unroll
    for (int p = 0; p < 4; p++) upk2(accp[p], o[2 * p], o[2 * p + 1]);
    float4 bA = __ldg((const float4*)(b2 + c0));
    float4 bB = __ldg((const float4*)(b2 + c0 + 4));
    o[0] = o[0] * inv + bA.x; o[1] = o[1] * inv + bA.y;
    o[2] = o[2] * inv + bA.z; o[3] = o[3] * inv + bA.w;
    o[4] = o[4] * inv + bB.x; o[5] = o[5] * inv + bB.y;
    o[6] = o[6] * inv + bB.z; o[7] = o[7] * inv + bB.w;

    // LayerNorm(128) across the 16-lane half
    float s = 0.f, s2 = 0.f;
#pragma unroll
    for (int j = 0; j < 8; j++) { s += o[j]; s2 += o[j] * o[j]; }
#pragma unroll
    for (int d = 8; d >= 1; d >>= 1) {
        s  += __shfl_xor_sync(0xffffffffu, s, d);
        s2 += __shfl_xor_sync(0xffffffffu, s2, d);
    }
    float mu = s * (1.f / 128.f);
    float var = s2 * (1.f / 128.f) - mu * mu;
    float rstd = rsqrtf(var + 1e-5f);
    float4 gA = __ldg((const float4*)(g2 + c0));
    float4 gB = __ldg((const float4*)(g2 + c0 + 4));
    float4 tA = __ldg((const float4*)(beta2 + c0));
    float4 tB = __ldg((const float4*)(beta2 + c0 + 4));
    float y[8];
    y[0] = (o[0]-mu)*rstd*gA.x + tA.x; y[1] = (o[1]-mu)*rstd*gA.y + tA.y;
    y[2] = (o[2]-mu)*rstd*gA.z + tA.z; y[3] = (o[3]-mu)*rstd*gA.w + tA.w;
    y[4] = (o[4]-mu)*rstd*gB.x + tB.x; y[5] = (o[5]-mu)*rstd*gB.y + tB.y;
    y[6] = (o[6]-mu)*rstd*gB.z + tB.z; y[7] = (o[7]-mu)*rstd*gB.w + tB.w;
#pragma unroll
    for (int j = 0; j < 8; j++) y[j] = (y[j] > 0.f) ? y[j] : (__expf(y[j]) - 1.f);
    float4* ph = (float4*)(d_h2 + (size_t)n * 128 + c0);
    ph[0] = make_float4(y[0], y[1], y[2], y[3]);
    ph[1] = make_float4(y[4], y[5], y[6], y[7]);
}

// pooling: block of 128 threads handles 32 consecutive nodes (batch is sorted)
__global__ void k_pool(const int* __restrict__ batch) {
    __shared__ int s_b[32];
    int n0 = blockIdx.x * 32;
    int tid = threadIdx.x;
    if (tid < 32) {
        int n = n0 + tid;
        s_b[tid] = (n < NN) ? batch[n] : -1;
    }
    __syncthreads();
    int c = tid;
    float acc = 0.f;
    int cur = s_b[0];
    for (int j = 0; j < 32; j++) {
        int n = n0 + j;
        if (n >= NN) break;
        int g = s_b[j];
        if (g != cur) {
            atomicAdd(&d_pool[cur * 128 + c], acc);
            acc = 0.f;
            cur = g;
        }
        acc += d_h2[(size_t)n * 128 + c];
    }
    atomicAdd(&d_pool[cur * 128 + c], acc);
    if (tid == 0) {
        int cg = s_b[0];
        float ct = 0.f;
        for (int j = 0; j < 32; j++) {
            int n = n0 + j;
            if (n >= NN) break;
            int g = s_b[j];
            if (g != cg) { atomicAdd(&d_cnt[cg], ct); ct = 0.f; cg = g; }
            ct += 1.f;
        }
        atomicAdd(&d_cnt[cg], ct);
    }
}

__global__ void k_pooldiv(float* __restrict__ out) {
    int g = blockIdx.x, c = threadIdx.x;
    out[g * 128 + c] = d_pool[g * 128 + c] / fmaxf(d_cnt[g], 1.f);
    d_pool[g * 128 + c] = 0.f;      // reset for next replay
    if (c == 0) d_cnt[g] = 0.f;
}

// ---------------------------------------------------------------------------
extern "C" void kernel_launch(void* const* d_in, const int* in_sizes, int n_in,
                              void* d_out, int out_size) {
    const float* x     = (const float*)d_in[0];
    const int*   ei    = (const int*)  d_in[1];
    const float* ea    = (const float*)d_in[2];
    const int*   batch = (const int*)  d_in[3];
    const float* Wl1   = (const float*)d_in[4];
    const float* Wr1   = (const float*)d_in[5];
    const float* We1   = (const float*)d_in[6];
    const float* att1  = (const float*)d_in[7];
    const float* b1    = (const float*)d_in[8];
    const float* g1    = (const float*)d_in[9];
    const float* beta1 = (const float*)d_in[10];
    const float* Wl2   = (const float*)d_in[11];
    const float* Wr2   = (const float*)d_in[12];
    const float* We2   = (const float*)d_in[13];
    const float* att2  = (const float*)d_in[14];
    const float* b2    = (const float*)d_in[15];
    const float* g2    = (const float*)d_in[16];
    const float* beta2 = (const float*)d_in[17];
    float* out = (float*)d_out;

    k_gfill<<<GEMM1_BLKS + FILL_BLKS, 256>>>(x, Wl1, ei, ea);         // #1
    k_fagg1<<<(NN + 7) / 8, 256>>>(x, Wr1, We1, att1, b1, g1, beta1); // #2
    k_gemm2<<<(NN + 127) / 128, 512>>>(Wl2, Wr2);                     // #3
    k_fagg2<<<NN / 16, 256>>>(We2, att2, b2, g2, beta2);              // #4 (profiled)
    k_pool<<<(NN + 31) / 32, 128>>>(batch);                           // #5
    k_pooldiv<<<NG, 128>>>(out);                                      // #6
}

// round 15
// speedup vs baseline: 1.1771x; 1.0542x over previous
#include <cuda_runtime.h>
#include <math.h>

#define NN 50000
#define NE 800000
#define NG 64
#define SLOT 96

typedef unsigned long long u64;
typedef unsigned int u32;

// ------------------- scratch (device globals; zero-initialized at load) ----
__device__ float d_xl1[NN * 256];
__device__ float d_h1 [NN * 256];
__device__ float d_xl2[NN * 128];
__device__ float d_xr2[NN * 128];
__device__ float d_h2 [NN * 128];
__device__ float d_loopsum[NN];
__device__ int   d_cursor[NN];
__device__ u64   d_sadj[(size_t)NN * SLOT];   // packed (ea:f32 hi, src:i32 lo)
__device__ float d_pool[NG * 128];
__device__ float d_cnt[NG];

// ---------------- packed f32x2 helpers --------------------------------------
__device__ __forceinline__ u64 pk2(float lo, float hi) {
    u64 r; asm("mov.b64 %0, {%1,%2};" : "=l"(r) : "f"(lo), "f"(hi)); return r;
}
__device__ __forceinline__ void upk2(u64 v, float& lo, float& hi) {
    asm("mov.b64 {%0,%1}, %2;" : "=f"(lo), "=f"(hi) : "l"(v));
}
__device__ __forceinline__ u64 add2(u64 a, u64 b) {
    u64 d; asm("add.rn.f32x2 %0, %1, %2;" : "=l"(d) : "l"(a), "l"(b)); return d;
}
__device__ __forceinline__ u64 mul2(u64 a, u64 b) {
    u64 d; asm("mul.rn.f32x2 %0, %1, %2;" : "=l"(d) : "l"(a), "l"(b)); return d;
}
__device__ __forceinline__ u64 fma2(u64 a, u64 b, u64 c) {
    u64 d; asm("fma.rn.f32x2 %0, %1, %2, %3;" : "=l"(d) : "l"(a), "l"(b), "l"(c)); return d;
}
#define ABS2 0x7FFFFFFF7FFFFFFFull

// packed GATv2 logit contribution: t = leaky(l + xr + eav*we); lg += t*at
__device__ __forceinline__ u64 gat2(u64 l, u64 xr, u64 we, u64 at, u64 eav2,
                                    u64 c06, u64 c04, u64 lg) {
    u64 t = add2(l, xr);
    t = fma2(eav2, we, t);
    u64 ab = t & ABS2;
    t = fma2(c04, ab, mul2(t, c06));    // = m>0 ? m : 0.2m
    return fma2(t, at, lg);
}

// safe exp: logits here are O(10); clamp is a never-hit overflow guard
__device__ __forceinline__ float sexp(float a) { return __expf(fminf(a, 80.f)); }

// ---------------------------------------------------------------------------
// FUSED: gemm1 (xl1 = x @ Wl1) + adjacency fill, split by block role
#define GEMM1_BLKS (NN / 4)           // 12500
#define FILL_BLKS  ((NE + 255) / 256) // 3125
__global__ void k_gfill(const float* __restrict__ x, const float* __restrict__ Wl,
                        const int* __restrict__ ei, const float* __restrict__ ea) {
    int tid = threadIdx.x;
    if (blockIdx.x < GEMM1_BLKS) {
        __shared__ float sx[32];
        int n0 = blockIdx.x * 4;
        if (tid < 32) sx[tid] = x[n0 * 8 + tid];
        __syncthreads();
        float w[8];
#pragma unroll
        for (int k = 0; k < 8; k++) w[k] = Wl[k * 256 + tid];
#pragma unroll
        for (int q = 0; q < 4; q++) {
            float a = 0.f;
#pragma unroll
            for (int k = 0; k < 8; k++) a += sx[q * 8 + k] * w[k];
            d_xl1[(size_t)(n0 + q) * 256 + tid] = a;
        }
    } else {
        int e = (blockIdx.x - GEMM1_BLKS) * 256 + tid;
        if (e < NE) {
            int dst = ei[NE + e];
            int src = ei[e];
            float v = ea[e];
            int p = atomicAdd(&d_cursor[dst], 1);
            if (p < SLOT)
                d_sadj[(size_t)dst * SLOT + p] =
                    ((u64)__float_as_uint(v) << 32) | (u32)src;
            atomicAdd(&d_loopsum[dst], v);
        }
    }
}

// ======== layer-1 FUSED, warp per node, unnormalized-exp softmax ============
// Lane owns channels [lane*8, lane*8+8); head = lane>>3 (8-lane segments).
__global__ __launch_bounds__(256, 4) void
k_fagg1(const float* __restrict__ x,
        const float* __restrict__ Wr, const float* __restrict__ We,
        const float* __restrict__ att,
        const float* __restrict__ b1, const float* __restrict__ g1,
        const float* __restrict__ beta1) {
    int wid = threadIdx.x >> 5, lane = threadIdx.x & 31;
    int n = blockIdx.x * 8 + wid;

    int cnt = d_cursor[n];
    if (cnt > SLOT) cnt = SLOT;
    float loopv = d_loopsum[n] / fmaxf((float)cnt, 1.f);

    int c0 = lane * 8;

    // xr row: x[n] (8) @ Wr (8x256), this lane's 8 channels (scalar, then pack)
    float xv = (lane < 8) ? x[n * 8 + lane] : 0.f;
    float xr[8];
#pragma unroll
    for (int j = 0; j < 8; j++) xr[j] = 0.f;
#pragma unroll
    for (int k = 0; k < 8; k++) {
        float xk = __shfl_sync(0xffffffffu, xv, k);
        float4 wA = __ldg((const float4*)(Wr + k * 256 + c0));
        float4 wB = __ldg((const float4*)(Wr + k * 256 + c0 + 4));
        xr[0] += xk * wA.x; xr[1] += xk * wA.y; xr[2] += xk * wA.z; xr[3] += xk * wA.w;
        xr[4] += xk * wB.x; xr[5] += xk * wB.y; xr[6] += xk * wB.z; xr[7] += xk * wB.w;
    }
    u64 xr2[4];
#pragma unroll
    for (int p = 0; p < 4; p++) xr2[p] = pk2(xr[2 * p], xr[2 * p + 1]);

    ulonglong2 weL = *(const ulonglong2*)(We + c0);
    ulonglong2 weH = *(const ulonglong2*)(We + c0 + 4);
    ulonglong2 atL = *(const ulonglong2*)(att + c0);
    ulonglong2 atH = *(const ulonglong2*)(att + c0 + 4);
    u64 we2[4] = {weL.x, weL.y, weH.x, weH.y};
    u64 at2[4] = {atL.x, atL.y, atH.x, atH.y};
    const u64 c06 = pk2(0.6f, 0.6f), c04 = pk2(0.4f, 0.4f);

    // ---- self-loop initialization (unnormalized) ----
    const ulonglong2* ps = (const ulonglong2*)(d_xl1 + (size_t)n * 256 + c0);
    ulonglong2 s0 = ps[0], s1 = ps[1];
    u64 sl[4] = {s0.x, s0.y, s1.x, s1.y};
    u64 accp[4];
    float dsum;
    {
        u64 eav2 = pk2(loopv, loopv);
        u64 lg = 0ull;
#pragma unroll
        for (int p = 0; p < 4; p++) lg = gat2(sl[p], xr2[p], we2[p], at2[p], eav2, c06, c04, lg);
        float lo, hi; upk2(lg, lo, hi);
        float a = lo + hi;
        a += __shfl_xor_sync(0xffffffffu, a, 1);
        a += __shfl_xor_sync(0xffffffffu, a, 2);
        a += __shfl_xor_sync(0xffffffffu, a, 4);
        float e0 = sexp(a);
        dsum = e0;
        u64 e02 = pk2(e0, e0);
#pragma unroll
        for (int p = 0; p < 4; p++) accp[p] = mul2(e02, sl[p]);
    }

    const size_t sbase = (size_t)n * SLOT;
    int i = 0;
    // ---- pairs of edges (iterations fully independent) ----
    for (; i + 1 < cnt; i += 2) {
        ulonglong2 pp = *(const ulonglong2*)(d_sadj + sbase + i);
        int   src1 = (int)(u32)pp.x; float ea1 = __uint_as_float((u32)(pp.x >> 32));
        int   src2 = (int)(u32)pp.y; float ea2 = __uint_as_float((u32)(pp.y >> 32));
        const ulonglong2* p1 = (const ulonglong2*)(d_xl1 + (size_t)src1 * 256 + c0);
        const ulonglong2* p2 = (const ulonglong2*)(d_xl1 + (size_t)src2 * 256 + c0);
        ulonglong2 l1a = p1[0], l1b = p1[1];
        ulonglong2 l2a = p2[0], l2b = p2[1];
        u64 l1[4] = {l1a.x, l1a.y, l1b.x, l1b.y};
        u64 l2[4] = {l2a.x, l2a.y, l2b.x, l2b.y};
        u64 ev1 = pk2(ea1, ea1), ev2 = pk2(ea2, ea2);
        u64 lg1 = 0ull, lg2 = 0ull;
#pragma unroll
        for (int p = 0; p < 4; p++) {
            lg1 = gat2(l1[p], xr2[p], we2[p], at2[p], ev1, c06, c04, lg1);
            lg2 = gat2(l2[p], xr2[p], we2[p], at2[p], ev2, c06, c04, lg2);
        }
        float lo1, hi1, lo2, hi2;
        upk2(lg1, lo1, hi1); upk2(lg2, lo2, hi2);
        float a1 = lo1 + hi1, a2 = lo2 + hi2;
        a1 += __shfl_xor_sync(0xffffffffu, a1, 1);
        a2 += __shfl_xor_sync(0xffffffffu, a2, 1);
        a1 += __shfl_xor_sync(0xffffffffu, a1, 2);
        a2 += __shfl_xor_sync(0xffffffffu, a2, 2);
        a1 += __shfl_xor_sync(0xffffffffu, a1, 4);
        a2 += __shfl_xor_sync(0xffffffffu, a2, 4);
        float e1 = sexp(a1);
        float e2 = sexp(a2);
        dsum += e1 + e2;
        u64 e12 = pk2(e1, e1), e22 = pk2(e2, e2);
#pragma unroll
        for (int p = 0; p < 4; p++)
            accp[p] = fma2(e22, l2[p], fma2(e12, l1[p], accp[p]));
    }
    // ---- odd tail edge ----
    if (i < cnt) {
        u64 p = d_sadj[sbase + i];
        int src1 = (int)(u32)p; float ea1 = __uint_as_float((u32)(p >> 32));
        const ulonglong2* p1 = (const ulonglong2*)(d_xl1 + (size_t)src1 * 256 + c0);
        ulonglong2 l1a = p1[0], l1b = p1[1];
        u64 l1[4] = {l1a.x, l1a.y, l1b.x, l1b.y};
        u64 ev1 = pk2(ea1, ea1);
        u64 lg1 = 0ull;
#pragma unroll
        for (int q = 0; q < 4; q++) lg1 = gat2(l1[q], xr2[q], we2[q], at2[q], ev1, c06, c04, lg1);
        float lo1, hi1; upk2(lg1, lo1, hi1);
        float a1 = lo1 + hi1;
        a1 += __shfl_xor_sync(0xffffffffu, a1, 1);
        a1 += __shfl_xor_sync(0xffffffffu, a1, 2);
        a1 += __shfl_xor_sync(0xffffffffu, a1, 4);
        float e1 = sexp(a1);
        dsum += e1;
        u64 e12 = pk2(e1, e1);
#pragma unroll
        for (int q = 0; q < 4; q++)
            accp[q] = fma2(e12, l1[q], accp[q]);
    }

    float inv = 1.f / (dsum + 1e-16f);
    float o[8];
#pragma unroll
    for (int p = 0; p < 4; p++) upk2(accp[p], o[2 * p], o[2 * p + 1]);
    float4 bA = __ldg((const float4*)(b1 + c0));
    float4 bB = __ldg((const float4*)(b1 + c0 + 4));
    o[0] = o[0] * inv + bA.x; o[1] = o[1] * inv + bA.y;
    o[2] = o[2] * inv + bA.z; o[3] = o[3] * inv + bA.w;
    o[4] = o[4] * inv + bB.x; o[5] = o[5] * inv + bB.y;
    o[6] = o[6] * inv + bB.z; o[7] = o[7] * inv + bB.w;

    // LayerNorm(256) across the warp
    float s = 0.f, s2 = 0.f;
#pragma unroll
    for (int j = 0; j < 8; j++) { s += o[j]; s2 += o[j] * o[j]; }
#pragma unroll
    for (int d = 16; d >= 1; d >>= 1) {
        s  += __shfl_xor_sync(0xffffffffu, s, d);
        s2 += __shfl_xor_sync(0xffffffffu, s2, d);
    }
    float mu = s * (1.f / 256.f);
    float var = s2 * (1.f / 256.f) - mu * mu;
    float rstd = rsqrtf(var + 1e-5f);
    float4 gA = __ldg((const float4*)(g1 + c0));
    float4 gB = __ldg((const float4*)(g1 + c0 + 4));
    float4 tA = __ldg((const float4*)(beta1 + c0));
    float4 tB = __ldg((const float4*)(beta1 + c0 + 4));
    float y[8];
    y[0] = (o[0]-mu)*rstd*gA.x + tA.x; y[1] = (o[1]-mu)*rstd*gA.y + tA.y;
    y[2] = (o[2]-mu)*rstd*gA.z + tA.z; y[3] = (o[3]-mu)*rstd*gA.w + tA.w;
    y[4] = (o[4]-mu)*rstd*gB.x + tB.x; y[5] = (o[5]-mu)*rstd*gB.y + tB.y;
    y[6] = (o[6]-mu)*rstd*gB.z + tB.z; y[7] = (o[7]-mu)*rstd*gB.w + tB.w;
#pragma unroll
    for (int j = 0; j < 8; j++) y[j] = (y[j] > 0.f) ? y[j] : (__expf(y[j]) - 1.f);
    float4* ph = (float4*)(d_h1 + (size_t)n * 256 + c0);
    ph[0] = make_float4(y[0], y[1], y[2], y[3]);
    ph[1] = make_float4(y[4], y[5], y[6], y[7]);
}

// ======== GEMM2 via tf32 mma.sync, SMEM-staged + reg prefetch ===============
__device__ __forceinline__ u32 f2tf(float f) {
    u32 u;
    asm("cvt.rna.tf32.f32 %0, %1;" : "=r"(u) : "f"(f));
    return u;
}
__device__ __forceinline__ void mma_tf32(float* d, const u32* a, u32 b0, u32 b1) {
    asm("mma.sync.aligned.m16n8k8.row.col.f32.tf32.tf32.f32 "
        "{%0,%1,%2,%3}, {%4,%5,%6,%7}, {%8,%9}, {%0,%1,%2,%3};"
        : "+f"(d[0]), "+f"(d[1]), "+f"(d[2]), "+f"(d[3])
        : "r"(a[0]), "r"(a[1]), "r"(a[2]), "r"(a[3]), "r"(b0), "r"(b1));
}

#define GK 16
__global__ __launch_bounds__(512) void
k_gemm2(const float* __restrict__ Wl, const float* __restrict__ Wr) {
    __shared__ u32 sA[128][20];
    __shared__ u32 sB[GK][264];
    int tid = threadIdx.x;
    int w = tid >> 5, lane = tid & 31;
    int gid = lane >> 2, tig = lane & 3;
    int mgrp = w >> 2, ngrp = w & 3;
    int row0 = blockIdx.x * 128;
    int wm0 = mgrp * 32;
    int wn0 = ngrp * 64;

    float d[2][8][4];
#pragma unroll
    for (int mt = 0; mt < 2; mt++)
#pragma unroll
        for (int nt = 0; nt < 8; nt++)
#pragma unroll
            for (int q = 0; q < 4; q++) d[mt][nt][q] = 0.f;

    int ar = tid >> 2, akq = tid & 3;
    int gr = min(row0 + ar, NN - 1);
    const float4* aptr = (const float4*)(d_h1 + (size_t)gr * 256 + akq * 4);
    int kr0 = tid >> 6,         cq0 = tid & 63;
    int kr1 = (tid + 512) >> 6, cq1 = (tid + 512) & 63;
    const float* bsrc0 = (cq0 < 32) ? (Wl + kr0 * 128 + cq0 * 4)
                                    : (Wr + kr0 * 128 + (cq0 - 32) * 4);
    const float* bsrc1 = (cq1 < 32) ? (Wl + kr1 * 128 + cq1 * 4)
                                    : (Wr + kr1 * 128 + (cq1 - 32) * 4);

    float4 va = aptr[0];
    float4 vb0 = *(const float4*)bsrc0;
    float4 vb1 = *(const float4*)bsrc1;

    for (int k0 = 0; k0 < 256; k0 += GK) {
        sA[ar][akq * 4 + 0] = f2tf(va.x);
        sA[ar][akq * 4 + 1] = f2tf(va.y);
        sA[ar][akq * 4 + 2] = f2tf(va.z);
        sA[ar][akq * 4 + 3] = f2tf(va.w);
        sB[kr0][cq0 * 4 + 0] = f2tf(vb0.x);
        sB[kr0][cq0 * 4 + 1] = f2tf(vb0.y);
        sB[kr0][cq0 * 4 + 2] = f2tf(vb0.z);
        sB[kr0][cq0 * 4 + 3] = f2tf(vb0.w);
        sB[kr1][cq1 * 4 + 0] = f2tf(vb1.x);
        sB[kr1][cq1 * 4 + 1] = f2tf(vb1.y);
        sB[kr1][cq1 * 4 + 2] = f2tf(vb1.z);
        sB[kr1][cq1 * 4 + 3] = f2tf(vb1.w);
        __syncthreads();
        if (k0 + GK < 256) {
            va  = aptr[(k0 + GK) >> 2];
            vb0 = *(const float4*)(bsrc0 + (size_t)(k0 + GK) * 128);
            vb1 = *(const float4*)(bsrc1 + (size_t)(k0 + GK) * 128);
        }
#pragma unroll
        for (int kk = 0; kk < GK; kk += 8) {
            u32 a[2][4];
            a[0][0] = sA[wm0 + gid][kk + tig];
            a[0][1] = sA[wm0 + gid + 8][kk + tig];
            a[0][2] = sA[wm0 + gid][kk + tig + 4];
            a[0][3] = sA[wm0 + gid + 8][kk + tig + 4];
            a[1][0] = sA[wm0 + 16 + gid][kk + tig];
            a[1][1] = sA[wm0 + 24 + gid][kk + tig];
            a[1][2] = sA[wm0 + 16 + gid][kk + tig + 4];
            a[1][3] = sA[wm0 + 24 + gid][kk + tig + 4];
#pragma unroll
            for (int nt = 0; nt < 8; nt++) {
                int c = wn0 + nt * 8 + gid;
                u32 b0 = sB[kk + tig][c];
                u32 b1 = sB[kk + tig + 4][c];
                mma_tf32(d[0][nt], a[0], b0, b1);
                mma_tf32(d[1][nt], a[1], b0, b1);
            }
        }
        __syncthreads();
    }

    float* OUT = (wn0 < 128) ? d_xl2 : d_xr2;
#pragma unroll
    for (int mt = 0; mt < 2; mt++) {
        int rA = row0 + wm0 + mt * 16 + gid;
        int rB = rA + 8;
#pragma unroll
        for (int nt = 0; nt < 8; nt++) {
            int cc = (wn0 + nt * 8 + 2 * tig) & 127;
            if (rA < NN)
                *(float2*)(OUT + (size_t)rA * 128 + cc) = make_float2(d[mt][nt][0], d[mt][nt][1]);
            if (rB < NN)
                *(float2*)(OUT + (size_t)rB * 128 + cc) = make_float2(d[mt][nt][2], d[mt][nt][3]);
        }
    }
}

// ======== layer-2 FUSED: 2 nodes per warp, COALESCED split-channel layout ===
// Lane owns channels [lane16*4,+4) and [64+lane16*4,+4) of node (wid*2+half).
// Each 16B gather is contiguous across the 16-lane group (2 lines vs 4).
__global__ __launch_bounds__(256, 4) void
k_fagg2(const float* __restrict__ We, const float* __restrict__ att,
        const float* __restrict__ b2, const float* __restrict__ g2,
        const float* __restrict__ beta2) {
    int wid = threadIdx.x >> 5, lane = threadIdx.x & 31;
    int half = lane >> 4, lane16 = lane & 15;
    int n = blockIdx.x * 16 + wid * 2 + half;

    int cnt = d_cursor[n];
    if (cnt > SLOT) cnt = SLOT;
    float loopv = d_loopsum[n] / fmaxf((float)cnt, 1.f);
    if (lane16 == 0) { d_cursor[n] = 0; d_loopsum[n] = 0.f; }

    int c0a = lane16 * 4;
    int c0b = 64 + lane16 * 4;
    const float* rowx = d_xr2 + (size_t)n * 128;
    ulonglong2 xrA = *(const ulonglong2*)(rowx + c0a);
    ulonglong2 xrB = *(const ulonglong2*)(rowx + c0b);
    u64 xr2v[4] = {xrA.x, xrA.y, xrB.x, xrB.y};
    ulonglong2 weA = *(const ulonglong2*)(We + c0a);
    ulonglong2 weB = *(const ulonglong2*)(We + c0b);
    ulonglong2 atA = *(const ulonglong2*)(att + c0a);
    ulonglong2 atB = *(const ulonglong2*)(att + c0b);
    u64 we2[4] = {weA.x, weA.y, weB.x, weB.y};
    u64 at2[4] = {atA.x, atA.y, atB.x, atB.y};
    const u64 c06 = pk2(0.6f, 0.6f), c04 = pk2(0.4f, 0.4f);

    // self-loop init (unnormalized)
    const float* rown = d_xl2 + (size_t)n * 128;
    ulonglong2 s0 = *(const ulonglong2*)(rown + c0a);
    ulonglong2 s1 = *(const ulonglong2*)(rown + c0b);
    u64 sl[4] = {s0.x, s0.y, s1.x, s1.y};
    u64 accp[4];
    float dsum;
    {
        u64 ev = pk2(loopv, loopv);
        u64 lg = 0ull;
#pragma unroll
        for (int p = 0; p < 4; p++) lg = gat2(sl[p], xr2v[p], we2[p], at2[p], ev, c06, c04, lg);
        float lo, hi; upk2(lg, lo, hi);
        float a = lo + hi;
        a += __shfl_xor_sync(0xffffffffu, a, 1);
        a += __shfl_xor_sync(0xffffffffu, a, 2);
        a += __shfl_xor_sync(0xffffffffu, a, 4);
        a += __shfl_xor_sync(0xffffffffu, a, 8);
        float e0 = sexp(a);
        dsum = e0;
        u64 e02 = pk2(e0, e0);
#pragma unroll
        for (int p = 0; p < 4; p++) accp[p] = mul2(e02, sl[p]);
    }

    // uniform loop bound across the warp (both nodes)
    int cnto = __shfl_xor_sync(0xffffffffu, cnt, 16);
    int maxc = max(cnt, cnto);

    const size_t sbase = (size_t)n * SLOT;
    int i = 0;
    for (; i + 1 < maxc; i += 2) {
        ulonglong2 pp = *(const ulonglong2*)(d_sadj + sbase + i);
        int   src1 = (int)(u32)pp.x; float ea1 = __uint_as_float((u32)(pp.x >> 32));
        int   src2 = (int)(u32)pp.y; float ea2 = __uint_as_float((u32)(pp.y >> 32));
        const float* r1 = d_xl2 + (size_t)src1 * 128;
        const float* r2 = d_xl2 + (size_t)src2 * 128;
        ulonglong2 l1a = *(const ulonglong2*)(r1 + c0a);
        ulonglong2 l1b = *(const ulonglong2*)(r1 + c0b);
        ulonglong2 l2a = *(const ulonglong2*)(r2 + c0a);
        ulonglong2 l2b = *(const ulonglong2*)(r2 + c0b);
        u64 l1[4] = {l1a.x, l1a.y, l1b.x, l1b.y};
        u64 l2[4] = {l2a.x, l2a.y, l2b.x, l2b.y};
        u64 ev1 = pk2(ea1, ea1), ev2 = pk2(ea2, ea2);
        u64 lg1 = 0ull, lg2 = 0ull;
#pragma unroll
        for (int p = 0; p < 4; p++) {
            lg1 = gat2(l1[p], xr2v[p], we2[p], at2[p], ev1, c06, c04, lg1);
            lg2 = gat2(l2[p], xr2v[p], we2[p], at2[p], ev2, c06, c04, lg2);
        }
        float lo1, hi1, lo2, hi2;
        upk2(lg1, lo1, hi1); upk2(lg2, lo2, hi2);
        float a1 = lo1 + hi1, a2 = lo2 + hi2;
        a1 += __shfl_xor_sync(0xffffffffu, a1, 1);
        a2 += __shfl_xor_sync(0xffffffffu, a2, 1);
        a1 += __shfl_xor_sync(0xffffffffu, a1, 2);
        a2 += __shfl_xor_sync(0xffffffffu, a2, 2);
        a1 += __shfl_xor_sync(0xffffffffu, a1, 4);
        a2 += __shfl_xor_sync(0xffffffffu, a2, 4);
        a1 += __shfl_xor_sync(0xffffffffu, a1, 8);
        a2 += __shfl_xor_sync(0xffffffffu, a2, 8);
        // mask edges beyond this node's own count (exp underflows to 0)
        if (i >= cnt)     a1 = -1e30f;
        if (i + 1 >= cnt) a2 = -1e30f;
        float e1 = sexp(a1);
        float e2 = sexp(a2);
        dsum += e1 + e2;
        u64 e12 = pk2(e1, e1), e22 = pk2(e2, e2);
#pragma unroll
        for (int p = 0; p < 4; p++)
            accp[p] = fma2(e22, l2[p], fma2(e12, l1[p], accp[p]));
    }
    if (i < maxc) {
        u64 p = d_sadj[sbase + i];
        int src1 = (int)(u32)p; float ea1 = __uint_as_float((u32)(p >> 32));
        const float* r1 = d_xl2 + (size_t)src1 * 128;
        ulonglong2 l1a = *(const ulonglong2*)(r1 + c0a);
        ulonglong2 l1b = *(const ulonglong2*)(r1 + c0b);
        u64 l1[4] = {l1a.x, l1a.y, l1b.x, l1b.y};
        u64 ev1 = pk2(ea1, ea1);
        u64 lg1 = 0ull;
#pragma unroll
        for (int q = 0; q < 4; q++) lg1 = gat2(l1[q], xr2v[q], we2[q], at2[q], ev1, c06, c04, lg1);
        float lo1, hi1; upk2(lg1, lo1, hi1);
        float a1 = lo1 + hi1;
        a1 += __shfl_xor_sync(0xffffffffu, a1, 1);
        a1 += __shfl_xor_sync(0xffffffffu, a1, 2);
        a1 += __shfl_xor_sync(0xffffffffu, a1, 4);
        a1 += __shfl_xor_sync(0xffffffffu, a1, 8);
        if (i >= cnt) a1 = -1e30f;
        float e1 = sexp(a1);
        dsum += e1;
        u64 e12 = pk2(e1, e1);
#pragma unroll
        for (int q = 0; q < 4; q++)
            accp[q] = fma2(e12, l1[q], accp[q]);
    }

    float inv = 1.f / (dsum + 1e-16f);
    float o[8];
#pragma unroll
    for (int p = 0; p < 4; p++) upk2(accp[p], o[2 * p], o[2 * p + 1]);
    float4 bA = __ldg((const float4*)(b2 + c0a));
    float4 bB = __ldg((const float4*)(b2 + c0b));
    o[0] = o[0] * inv + bA.x; o[1] = o[1] * inv + bA.y;
    o[2] = o[2] * inv + bA.z; o[3] = o[3] * inv + bA.w;
    o[4] = o[4] * inv + bB.x; o[5] = o[5] * inv + bB.y;
    o[6] = o[6] * inv + bB.z; o[7] = o[7] * inv + bB.w;

    // LayerNorm(128) across the 16-lane half
    float s = 0.f, s2 = 0.f;
#pragma unroll
    for (int j = 0; j < 8; j++) { s += o[j]; s2 += o[j] * o[j]; }
#pragma unroll
    for (int d = 8; d >= 1; d >>= 1) {
        s  += __shfl_xor_sync(0xffffffffu, s, d);
        s2 += __shfl_xor_sync(0xffffffffu, s2, d);
    }
    float mu = s * (1.f / 128.f);
    float var = s2 * (1.f / 128.f) - mu * mu;
    float rstd = rsqrtf(var + 1e-5f);
    float4 gA = __ldg((const float4*)(g2 + c0a));
    float4 gB = __ldg((const float4*)(g2 + c0b));
    float4 tA = __ldg((const float4*)(beta2 + c0a));
    float4 tB = __ldg((const float4*)(beta2 + c0b));
    float y[8];
    y[0] = (o[0]-mu)*rstd*gA.x + tA.x; y[1] = (o[1]-mu)*rstd*gA.y + tA.y;
    y[2] = (o[2]-mu)*rstd*gA.z + tA.z; y[3] = (o[3]-mu)*rstd*gA.w + tA.w;
    y[4] = (o[4]-mu)*rstd*gB.x + tB.x; y[5] = (o[5]-mu)*rstd*gB.y + tB.y;
    y[6] = (o[6]-mu)*rstd*gB.z + tB.z; y[7] = (o[7]-mu)*rstd*gB.w + tB.w;
#pragma unroll
    for (int j = 0; j < 8; j++) y[j] = (y[j] > 0.f) ? y[j] : (__expf(y[j]) - 1.f);
    float* ph = d_h2 + (size_t)n * 128;
    *(float4*)(ph + c0a) = make_float4(y[0], y[1], y[2], y[3]);
    *(float4*)(ph + c0b) = make_float4(y[4], y[5], y[6], y[7]);
}

// pooling: block of 128 threads handles 32 consecutive nodes (batch is sorted)
__global__ void k_pool(const int* __restrict__ batch) {
    __shared__ int s_b[32];
    int n0 = blockIdx.x * 32;
    int tid = threadIdx.x;
    if (tid < 32) {
        int n = n0 + tid;
        s_b[tid] = (n < NN) ? batch[n] : -1;
    }
    __syncthreads();
    int c = tid;
    float acc = 0.f;
    int cur = s_b[0];
    for (int j = 0; j < 32; j++) {
        int n = n0 + j;
        if (n >= NN) break;
        int g = s_b[j];
        if (g != cur) {
            atomicAdd(&d_pool[cur * 128 + c], acc);
            acc = 0.f;
            cur = g;
        }
        acc += d_h2[(size_t)n * 128 + c];
    }
    atomicAdd(&d_pool[cur * 128 + c], acc);
    if (tid == 0) {
        int cg = s_b[0];
        float ct = 0.f;
        for (int j = 0; j < 32; j++) {
            int n = n0 + j;
            if (n >= NN) break;
            int g = s_b[j];
            if (g != cg) { atomicAdd(&d_cnt[cg], ct); ct = 0.f; cg = g; }
            ct += 1.f;
        }
        atomicAdd(&d_cnt[cg], ct);
    }
}

__global__ void k_pooldiv(float* __restrict__ out) {
    int g = blockIdx.x, c = threadIdx.x;
    out[g * 128 + c] = d_pool[g * 128 + c] / fmaxf(d_cnt[g], 1.f);
    d_pool[g * 128 + c] = 0.f;      // reset for next replay
    if (c == 0) d_cnt[g] = 0.f;
}

// ---------------------------------------------------------------------------
extern "C" void kernel_launch(void* const* d_in, const int* in_sizes, int n_in,
                              void* d_out, int out_size) {
    const float* x     = (const float*)d_in[0];
    const int*   ei    = (const int*)  d_in[1];
    const float* ea    = (const float*)d_in[2];
    const int*   batch = (const int*)  d_in[3];
    const float* Wl1   = (const float*)d_in[4];
    const float* Wr1   = (const float*)d_in[5];
    const float* We1   = (const float*)d_in[6];
    const float* att1  = (const float*)d_in[7];
    const float* b1    = (const float*)d_in[8];
    const float* g1    = (const float*)d_in[9];
    const float* beta1 = (const float*)d_in[10];
    const float* Wl2   = (const float*)d_in[11];
    const float* Wr2   = (const float*)d_in[12];
    const float* We2   = (const float*)d_in[13];
    const float* att2  = (const float*)d_in[14];
    const float* b2    = (const float*)d_in[15];
    const float* g2    = (const float*)d_in[16];
    const float* beta2 = (const float*)d_in[17];
    float* out = (float*)d_out;

    k_gfill<<<GEMM1_BLKS + FILL_BLKS, 256>>>(x, Wl1, ei, ea);         // #1
    k_fagg1<<<(NN + 7) / 8, 256>>>(x, Wr1, We1, att1, b1, g1, beta1); // #2
    k_gemm2<<<(NN + 127) / 128, 512>>>(Wl2, Wr2);                     // #3
    k_fagg2<<<NN / 16, 256>>>(We2, att2, b2, g2, beta2);              // #4 (profiled)
    k_pool<<<(NN + 31) / 32, 128>>>(batch);                           // #5
    k_pooldiv<<<NG, 128>>>(out);                                      // #6
}

// round 16
// speedup vs baseline: 1.2599x; 1.0703x over previous
#include <cuda_runtime.h>
#include <math.h>

#define NN 50000
#define NE 800000
#define NG 64
#define SLOT 96

typedef unsigned long long u64;
typedef unsigned int u32;

// ------------------- scratch (device globals; zero-initialized at load) ----
__device__ float d_xl1[NN * 256];
__device__ float d_h1 [NN * 256];
__device__ float d_xl2[NN * 128];
__device__ float d_xr2[NN * 128];
__device__ float d_h2 [NN * 128];
__device__ float d_loopsum[NN];
__device__ int   d_cursor[NN];
__device__ u64   d_sadj[(size_t)NN * SLOT];   // packed (ea:f32 hi, src:i32 lo)
__device__ float d_pool[NG * 128];
__device__ float d_cnt[NG];

// ---------------- packed f32x2 helpers --------------------------------------
__device__ __forceinline__ u64 pk2(float lo, float hi) {
    u64 r; asm("mov.b64 %0, {%1,%2};" : "=l"(r) : "f"(lo), "f"(hi)); return r;
}
__device__ __forceinline__ void upk2(u64 v, float& lo, float& hi) {
    asm("mov.b64 {%0,%1}, %2;" : "=f"(lo), "=f"(hi) : "l"(v));
}
__device__ __forceinline__ u64 add2(u64 a, u64 b) {
    u64 d; asm("add.rn.f32x2 %0, %1, %2;" : "=l"(d) : "l"(a), "l"(b)); return d;
}
__device__ __forceinline__ u64 mul2(u64 a, u64 b) {
    u64 d; asm("mul.rn.f32x2 %0, %1, %2;" : "=l"(d) : "l"(a), "l"(b)); return d;
}
__device__ __forceinline__ u64 fma2(u64 a, u64 b, u64 c) {
    u64 d; asm("fma.rn.f32x2 %0, %1, %2, %3;" : "=l"(d) : "l"(a), "l"(b), "l"(c)); return d;
}
#define ABS2 0x7FFFFFFF7FFFFFFFull

// packed GATv2 logit contribution: t = leaky(l + xr + eav*we); lg += t*at
__device__ __forceinline__ u64 gat2(u64 l, u64 xr, u64 we, u64 at, u64 eav2,
                                    u64 c06, u64 c04, u64 lg) {
    u64 t = add2(l, xr);
    t = fma2(eav2, we, t);
    u64 ab = t & ABS2;
    t = fma2(c04, ab, mul2(t, c06));    // = m>0 ? m : 0.2m
    return fma2(t, at, lg);
}

// safe exp: logits here are O(10); clamp is a never-hit overflow guard
__device__ __forceinline__ float sexp(float a) { return __expf(fminf(a, 80.f)); }

// ---------------------------------------------------------------------------
// gemm1: xl1 = x @ Wl1 (K=8). 4 nodes per block, 256 threads.
__global__ void k_gemm1(const float* __restrict__ x, const float* __restrict__ Wl) {
    __shared__ float sx[32];
    int n0 = blockIdx.x * 4;
    int tid = threadIdx.x;
    if (tid < 32) sx[tid] = x[n0 * 8 + tid];
    __syncthreads();
    float w[8];
#pragma unroll
    for (int k = 0; k < 8; k++) w[k] = Wl[k * 256 + tid];
#pragma unroll
    for (int q = 0; q < 4; q++) {
        float a = 0.f;
#pragma unroll
        for (int k = 0; k < 8; k++) a += sx[q * 8 + k] * w[k];
        d_xl1[(size_t)(n0 + q) * 256 + tid] = a;
    }
}

// adjacency fill (half range per launch): slot table keyed by dst
__global__ void k_fill(const int* __restrict__ ei, const float* __restrict__ ea,
                       int e0, int e1) {
    int e = e0 + blockIdx.x * 256 + threadIdx.x;
    if (e < e1) {
        int dst = ei[NE + e];
        int src = ei[e];
        float v = ea[e];
        int p = atomicAdd(&d_cursor[dst], 1);
        if (p < SLOT)
            d_sadj[(size_t)dst * SLOT + p] =
                ((u64)__float_as_uint(v) << 32) | (u32)src;
        atomicAdd(&d_loopsum[dst], v);
    }
}

// ======== layer-1 FUSED, warp per node, COALESCED head-aligned layout =======
// head = lane>>3; lane owns channels [head*64+(lane&7)*4,+4) and +32.
// Each 16B gather: 4x contiguous 128B chunks per warp (4 lines vs 8).
__global__ __launch_bounds__(256, 4) void
k_fagg1(const float* __restrict__ x,
        const float* __restrict__ Wr, const float* __restrict__ We,
        const float* __restrict__ att,
        const float* __restrict__ b1, const float* __restrict__ g1,
        const float* __restrict__ beta1) {
    int wid = threadIdx.x >> 5, lane = threadIdx.x & 31;
    int n = blockIdx.x * 8 + wid;

    int cnt = d_cursor[n];
    if (cnt > SLOT) cnt = SLOT;
    float loopv = d_loopsum[n] / fmaxf((float)cnt, 1.f);

    int head = lane >> 3, l8 = lane & 7;
    int c0a = head * 64 + l8 * 4;
    int c0b = c0a + 32;

    // xr row: x[n] (8) @ Wr (8x256), this lane's 8 channels (scalar, then pack)
    float xv = (lane < 8) ? x[n * 8 + lane] : 0.f;
    float xra[4] = {0.f, 0.f, 0.f, 0.f}, xrb[4] = {0.f, 0.f, 0.f, 0.f};
#pragma unroll
    for (int k = 0; k < 8; k++) {
        float xk = __shfl_sync(0xffffffffu, xv, k);
        float4 wA = __ldg((const float4*)(Wr + k * 256 + c0a));
        float4 wB = __ldg((const float4*)(Wr + k * 256 + c0b));
        xra[0] += xk * wA.x; xra[1] += xk * wA.y; xra[2] += xk * wA.z; xra[3] += xk * wA.w;
        xrb[0] += xk * wB.x; xrb[1] += xk * wB.y; xrb[2] += xk * wB.z; xrb[3] += xk * wB.w;
    }
    u64 xr2[4];
    xr2[0] = pk2(xra[0], xra[1]); xr2[1] = pk2(xra[2], xra[3]);
    xr2[2] = pk2(xrb[0], xrb[1]); xr2[3] = pk2(xrb[2], xrb[3]);

    ulonglong2 weL = *(const ulonglong2*)(We + c0a);
    ulonglong2 weH = *(const ulonglong2*)(We + c0b);
    ulonglong2 atL = *(const ulonglong2*)(att + c0a);
    ulonglong2 atH = *(const ulonglong2*)(att + c0b);
    u64 we2[4] = {weL.x, weL.y, weH.x, weH.y};
    u64 at2[4] = {atL.x, atL.y, atH.x, atH.y};
    const u64 c06 = pk2(0.6f, 0.6f), c04 = pk2(0.4f, 0.4f);

    // ---- self-loop initialization (unnormalized) ----
    const float* rown = d_xl1 + (size_t)n * 256;
    ulonglong2 s0 = *(const ulonglong2*)(rown + c0a);
    ulonglong2 s1 = *(const ulonglong2*)(rown + c0b);
    u64 sl[4] = {s0.x, s0.y, s1.x, s1.y};
    u64 accp[4];
    float dsum;
    {
        u64 eav2 = pk2(loopv, loopv);
        u64 lg = 0ull;
#pragma unroll
        for (int p = 0; p < 4; p++) lg = gat2(sl[p], xr2[p], we2[p], at2[p], eav2, c06, c04, lg);
        float lo, hi; upk2(lg, lo, hi);
        float a = lo + hi;
        a += __shfl_xor_sync(0xffffffffu, a, 1);
        a += __shfl_xor_sync(0xffffffffu, a, 2);
        a += __shfl_xor_sync(0xffffffffu, a, 4);
        float e0 = sexp(a);
        dsum = e0;
        u64 e02 = pk2(e0, e0);
#pragma unroll
        for (int p = 0; p < 4; p++) accp[p] = mul2(e02, sl[p]);
    }

    const size_t sbase = (size_t)n * SLOT;
    int i = 0;
    // ---- pairs of edges (iterations fully independent) ----
    for (; i + 1 < cnt; i += 2) {
        ulonglong2 pp = *(const ulonglong2*)(d_sadj + sbase + i);
        int   src1 = (int)(u32)pp.x; float ea1 = __uint_as_float((u32)(pp.x >> 32));
        int   src2 = (int)(u32)pp.y; float ea2 = __uint_as_float((u32)(pp.y >> 32));
        const float* r1 = d_xl1 + (size_t)src1 * 256;
        const float* r2 = d_xl1 + (size_t)src2 * 256;
        ulonglong2 l1a = *(const ulonglong2*)(r1 + c0a);
        ulonglong2 l1b = *(const ulonglong2*)(r1 + c0b);
        ulonglong2 l2a = *(const ulonglong2*)(r2 + c0a);
        ulonglong2 l2b = *(const ulonglong2*)(r2 + c0b);
        u64 l1[4] = {l1a.x, l1a.y, l1b.x, l1b.y};
        u64 l2[4] = {l2a.x, l2a.y, l2b.x, l2b.y};
        u64 ev1 = pk2(ea1, ea1), ev2 = pk2(ea2, ea2);
        u64 lg1 = 0ull, lg2 = 0ull;
#pragma unroll
        for (int p = 0; p < 4; p++) {
            lg1 = gat2(l1[p], xr2[p], we2[p], at2[p], ev1, c06, c04, lg1);
            lg2 = gat2(l2[p], xr2[p], we2[p], at2[p], ev2, c06, c04, lg2);
        }
        float lo1, hi1, lo2, hi2;
        upk2(lg1, lo1, hi1); upk2(lg2, lo2, hi2);
        float a1 = lo1 + hi1, a2 = lo2 + hi2;
        a1 += __shfl_xor_sync(0xffffffffu, a1, 1);
        a2 += __shfl_xor_sync(0xffffffffu, a2, 1);
        a1 += __shfl_xor_sync(0xffffffffu, a1, 2);
        a2 += __shfl_xor_sync(0xffffffffu, a2, 2);
        a1 += __shfl_xor_sync(0xffffffffu, a1, 4);
        a2 += __shfl_xor_sync(0xffffffffu, a2, 4);
        float e1 = sexp(a1);
        float e2 = sexp(a2);
        dsum += e1 + e2;
        u64 e12 = pk2(e1, e1), e22 = pk2(e2, e2);
#pragma unroll
        for (int p = 0; p < 4; p++)
            accp[p] = fma2(e22, l2[p], fma2(e12, l1[p], accp[p]));
    }
    // ---- odd tail edge ----
    if (i < cnt) {
        u64 p = d_sadj[sbase + i];
        int src1 = (int)(u32)p; float ea1 = __uint_as_float((u32)(p >> 32));
        const float* r1 = d_xl1 + (size_t)src1 * 256;
        ulonglong2 l1a = *(const ulonglong2*)(r1 + c0a);
        ulonglong2 l1b = *(const ulonglong2*)(r1 + c0b);
        u64 l1[4] = {l1a.x, l1a.y, l1b.x, l1b.y};
        u64 ev1 = pk2(ea1, ea1);
        u64 lg1 = 0ull;
#pragma unroll
        for (int q = 0; q < 4; q++) lg1 = gat2(l1[q], xr2[q], we2[q], at2[q], ev1, c06, c04, lg1);
        float lo1, hi1; upk2(lg1, lo1, hi1);
        float a1 = lo1 + hi1;
        a1 += __shfl_xor_sync(0xffffffffu, a1, 1);
        a1 += __shfl_xor_sync(0xffffffffu, a1, 2);
        a1 += __shfl_xor_sync(0xffffffffu, a1, 4);
        float e1 = sexp(a1);
        dsum += e1;
        u64 e12 = pk2(e1, e1);
#pragma unroll
        for (int q = 0; q < 4; q++)
            accp[q] = fma2(e12, l1[q], accp[q]);
    }

    float inv = 1.f / (dsum + 1e-16f);
    float o[8];
#pragma unroll
    for (int p = 0; p < 4; p++) upk2(accp[p], o[2 * p], o[2 * p + 1]);
    float4 bA = __ldg((const float4*)(b1 + c0a));
    float4 bB = __ldg((const float4*)(b1 + c0b));
    o[0] = o[0] * inv + bA.x; o[1] = o[1] * inv + bA.y;
    o[2] = o[2] * inv + bA.z; o[3] = o[3] * inv + bA.w;
    o[4] = o[4] * inv + bB.x; o[5] = o[5] * inv + bB.y;
    o[6] = o[6] * inv + bB.z; o[7] = o[7] * inv + bB.w;

    // LayerNorm(256) across the warp
    float s = 0.f, s2 = 0.f;
#pragma unroll
    for (int j = 0; j < 8; j++) { s += o[j]; s2 += o[j] * o[j]; }
#pragma unroll
    for (int d = 16; d >= 1; d >>= 1) {
        s  += __shfl_xor_sync(0xffffffffu, s, d);
        s2 += __shfl_xor_sync(0xffffffffu, s2, d);
    }
    float mu = s * (1.f / 256.f);
    float var = s2 * (1.f / 256.f) - mu * mu;
    float rstd = rsqrtf(var + 1e-5f);
    float4 gA = __ldg((const float4*)(g1 + c0a));
    float4 gB = __ldg((const float4*)(g1 + c0b));
    float4 tA = __ldg((const float4*)(beta1 + c0a));
    float4 tB = __ldg((const float4*)(beta1 + c0b));
    float y[8];
    y[0] = (o[0]-mu)*rstd*gA.x + tA.x; y[1] = (o[1]-mu)*rstd*gA.y + tA.y;
    y[2] = (o[2]-mu)*rstd*gA.z + tA.z; y[3] = (o[3]-mu)*rstd*gA.w + tA.w;
    y[4] = (o[4]-mu)*rstd*gB.x + tB.x; y[5] = (o[5]-mu)*rstd*gB.y + tB.y;
    y[6] = (o[6]-mu)*rstd*gB.z + tB.z; y[7] = (o[7]-mu)*rstd*gB.w + tB.w;
#pragma unroll
    for (int j = 0; j < 8; j++) y[j] = (y[j] > 0.f) ? y[j] : (__expf(y[j]) - 1.f);
    float* ph = d_h1 + (size_t)n * 256;
    *(float4*)(ph + c0a) = make_float4(y[0], y[1], y[2], y[3]);
    *(float4*)(ph + c0b) = make_float4(y[4], y[5], y[6], y[7]);
}

// ======== GEMM2 via tf32 mma.sync, SMEM-staged + reg prefetch ===============
__device__ __forceinline__ u32 f2tf(float f) {
    u32 u;
    asm("cvt.rna.tf32.f32 %0, %1;" : "=r"(u) : "f"(f));
    return u;
}
__device__ __forceinline__ void mma_tf32(float* d, const u32* a, u32 b0, u32 b1) {
    asm("mma.sync.aligned.m16n8k8.row.col.f32.tf32.tf32.f32 "
        "{%0,%1,%2,%3}, {%4,%5,%6,%7}, {%8,%9}, {%0,%1,%2,%3};"
        : "+f"(d[0]), "+f"(d[1]), "+f"(d[2]), "+f"(d[3])
        : "r"(a[0]), "r"(a[1]), "r"(a[2]), "r"(a[3]), "r"(b0), "r"(b1));
}

#define GK 16
__global__ __launch_bounds__(512) void
k_gemm2(const float* __restrict__ Wl, const float* __restrict__ Wr) {
    __shared__ u32 sA[128][20];
    __shared__ u32 sB[GK][264];
    int tid = threadIdx.x;
    int w = tid >> 5, lane = tid & 31;
    int gid = lane >> 2, tig = lane & 3;
    int mgrp = w >> 2, ngrp = w & 3;
    int row0 = blockIdx.x * 128;
    int wm0 = mgrp * 32;
    int wn0 = ngrp * 64;

    float d[2][8][4];
#pragma unroll
    for (int mt = 0; mt < 2; mt++)
#pragma unroll
        for (int nt = 0; nt < 8; nt++)
#pragma unroll
            for (int q = 0; q < 4; q++) d[mt][nt][q] = 0.f;

    int ar = tid >> 2, akq = tid & 3;
    int gr = min(row0 + ar, NN - 1);
    const float4* aptr = (const float4*)(d_h1 + (size_t)gr * 256 + akq * 4);
    int kr0 = tid >> 6,         cq0 = tid & 63;
    int kr1 = (tid + 512) >> 6, cq1 = (tid + 512) & 63;
    const float* bsrc0 = (cq0 < 32) ? (Wl + kr0 * 128 + cq0 * 4)
                                    : (Wr + kr0 * 128 + (cq0 - 32) * 4);
    const float* bsrc1 = (cq1 < 32) ? (Wl + kr1 * 128 + cq1 * 4)
                                    : (Wr + kr1 * 128 + (cq1 - 32) * 4);

    float4 va = aptr[0];
    float4 vb0 = *(const float4*)bsrc0;
    float4 vb1 = *(const float4*)bsrc1;

    for (int k0 = 0; k0 < 256; k0 += GK) {
        sA[ar][akq * 4 + 0] = f2tf(va.x);
        sA[ar][akq * 4 + 1] = f2tf(va.y);
        sA[ar][akq * 4 + 2] = f2tf(va.z);
        sA[ar][akq * 4 + 3] = f2tf(va.w);
        sB[kr0][cq0 * 4 + 0] = f2tf(vb0.x);
        sB[kr0][cq0 * 4 + 1] = f2tf(vb0.y);
        sB[kr0][cq0 * 4 + 2] = f2tf(vb0.z);
        sB[kr0][cq0 * 4 + 3] = f2tf(vb0.w);
        sB[kr1][cq1 * 4 + 0] = f2tf(vb1.x);
        sB[kr1][cq1 * 4 + 1] = f2tf(vb1.y);
        sB[kr1][cq1 * 4 + 2] = f2tf(vb1.z);
        sB[kr1][cq1 * 4 + 3] = f2tf(vb1.w);
        __syncthreads();
        if (k0 + GK < 256) {
            va  = aptr[(k0 + GK) >> 2];
            vb0 = *(const float4*)(bsrc0 + (size_t)(k0 + GK) * 128);
            vb1 = *(const float4*)(bsrc1 + (size_t)(k0 + GK) * 128);
        }
#pragma unroll
        for (int kk = 0; kk < GK; kk += 8) {
            u32 a[2][4];
            a[0][0] = sA[wm0 + gid][kk + tig];
            a[0][1] = sA[wm0 + gid + 8][kk + tig];
            a[0][2] = sA[wm0 + gid][kk + tig + 4];
            a[0][3] = sA[wm0 + gid + 8][kk + tig + 4];
            a[1][0] = sA[wm0 + 16 + gid][kk + tig];
            a[1][1] = sA[wm0 + 24 + gid][kk + tig];
            a[1][2] = sA[wm0 + 16 + gid][kk + tig + 4];
            a[1][3] = sA[wm0 + 24 + gid][kk + tig + 4];
#pragma unroll
            for (int nt = 0; nt < 8; nt++) {
                int c = wn0 + nt * 8 + gid;
                u32 b0 = sB[kk + tig][c];
                u32 b1 = sB[kk + tig + 4][c];
                mma_tf32(d[0][nt], a[0], b0, b1);
                mma_tf32(d[1][nt], a[1], b0, b1);
            }
        }
        __syncthreads();
    }

    float* OUT = (wn0 < 128) ? d_xl2 : d_xr2;
#pragma unroll
    for (int mt = 0; mt < 2; mt++) {
        int rA = row0 + wm0 + mt * 16 + gid;
        int rB = rA + 8;
#pragma unroll
        for (int nt = 0; nt < 8; nt++) {
            int cc = (wn0 + nt * 8 + 2 * tig) & 127;
            if (rA < NN)
                *(float2*)(OUT + (size_t)rA * 128 + cc) = make_float2(d[mt][nt][0], d[mt][nt][1]);
            if (rB < NN)
                *(float2*)(OUT + (size_t)rB * 128 + cc) = make_float2(d[mt][nt][2], d[mt][nt][3]);
        }
    }
}

// ======== layer-2 FUSED: 2 nodes per warp, COALESCED split-channel layout ===
// Lane owns channels [lane16*4,+4) and [64+lane16*4,+4) of node (wid*2+half).
__global__ __launch_bounds__(256, 4) void
k_fagg2(const float* __restrict__ We, const float* __restrict__ att,
        const float* __restrict__ b2, const float* __restrict__ g2,
        const float* __restrict__ beta2) {
    int wid = threadIdx.x >> 5, lane = threadIdx.x & 31;
    int half = lane >> 4, lane16 = lane & 15;
    int n = blockIdx.x * 16 + wid * 2 + half;

    int cnt = d_cursor[n];
    if (cnt > SLOT) cnt = SLOT;
    float loopv = d_loopsum[n] / fmaxf((float)cnt, 1.f);
    if (lane16 == 0) { d_cursor[n] = 0; d_loopsum[n] = 0.f; }

    int c0a = lane16 * 4;
    int c0b = 64 + lane16 * 4;
    const float* rowx = d_xr2 + (size_t)n * 128;
    ulonglong2 xrA = *(const ulonglong2*)(rowx + c0a);
    ulonglong2 xrB = *(const ulonglong2*)(rowx + c0b);
    u64 xr2v[4] = {xrA.x, xrA.y, xrB.x, xrB.y};
    ulonglong2 weA = *(const ulonglong2*)(We + c0a);
    ulonglong2 weB = *(const ulonglong2*)(We + c0b);
    ulonglong2 atA = *(const ulonglong2*)(att + c0a);
    ulonglong2 atB = *(const ulonglong2*)(att + c0b);
    u64 we2[4] = {weA.x, weA.y, weB.x, weB.y};
    u64 at2[4] = {atA.x, atA.y, atB.x, atB.y};
    const u64 c06 = pk2(0.6f, 0.6f), c04 = pk2(0.4f, 0.4f);

    // self-loop init (unnormalized)
    const float* rown = d_xl2 + (size_t)n * 128;
    ulonglong2 s0 = *(const ulonglong2*)(rown + c0a);
    ulonglong2 s1 = *(const ulonglong2*)(rown + c0b);
    u64 sl[4] = {s0.x, s0.y, s1.x, s1.y};
    u64 accp[4];
    float dsum;
    {
        u64 ev = pk2(loopv, loopv);
        u64 lg = 0ull;
#pragma unroll
        for (int p = 0; p < 4; p++) lg = gat2(sl[p], xr2v[p], we2[p], at2[p], ev, c06, c04, lg);
        float lo, hi; upk2(lg, lo, hi);
        float a = lo + hi;
        a += __shfl_xor_sync(0xffffffffu, a, 1);
        a += __shfl_xor_sync(0xffffffffu, a, 2);
        a += __shfl_xor_sync(0xffffffffu, a, 4);
        a += __shfl_xor_sync(0xffffffffu, a, 8);
        float e0 = sexp(a);
        dsum = e0;
        u64 e02 = pk2(e0, e0);
#pragma unroll
        for (int p = 0; p < 4; p++) accp[p] = mul2(e02, sl[p]);
    }

    // uniform loop bound across the warp (both nodes)
    int cnto = __shfl_xor_sync(0xffffffffu, cnt, 16);
    int maxc = max(cnt, cnto);

    const size_t sbase = (size_t)n * SLOT;
    int i = 0;
    for (; i + 1 < maxc; i += 2) {
        ulonglong2 pp = *(const ulonglong2*)(d_sadj + sbase + i);
        int   src1 = (int)(u32)pp.x; float ea1 = __uint_as_float((u32)(pp.x >> 32));
        int   src2 = (int)(u32)pp.y; float ea2 = __uint_as_float((u32)(pp.y >> 32));
        const float* r1 = d_xl2 + (size_t)src1 * 128;
        const float* r2 = d_xl2 + (size_t)src2 * 128;
        ulonglong2 l1a = *(const ulonglong2*)(r1 + c0a);
        ulonglong2 l1b = *(const ulonglong2*)(r1 + c0b);
        ulonglong2 l2a = *(const ulonglong2*)(r2 + c0a);
        ulonglong2 l2b = *(const ulonglong2*)(r2 + c0b);
        u64 l1[4] = {l1a.x, l1a.y, l1b.x, l1b.y};
        u64 l2[4] = {l2a.x, l2a.y, l2b.x, l2b.y};
        u64 ev1 = pk2(ea1, ea1), ev2 = pk2(ea2, ea2);
        u64 lg1 = 0ull, lg2 = 0ull;
#pragma unroll
        for (int p = 0; p < 4; p++) {
            lg1 = gat2(l1[p], xr2v[p], we2[p], at2[p], ev1, c06, c04, lg1);
            lg2 = gat2(l2[p], xr2v[p], we2[p], at2[p], ev2, c06, c04, lg2);
        }
        float lo1, hi1, lo2, hi2;
        upk2(lg1, lo1, hi1); upk2(lg2, lo2, hi2);
        float a1 = lo1 + hi1, a2 = lo2 + hi2;
        a1 += __shfl_xor_sync(0xffffffffu, a1, 1);
        a2 += __shfl_xor_sync(0xffffffffu, a2, 1);
        a1 += __shfl_xor_sync(0xffffffffu, a1, 2);
        a2 += __shfl_xor_sync(0xffffffffu, a2, 2);
        a1 += __shfl_xor_sync(0xffffffffu, a1, 4);
        a2 += __shfl_xor_sync(0xffffffffu, a2, 4);
        a1 += __shfl_xor_sync(0xffffffffu, a1, 8);
        a2 += __shfl_xor_sync(0xffffffffu, a2, 8);
        // mask edges beyond this node's own count (exp underflows to 0)
        if (i >= cnt)     a1 = -1e30f;
        if (i + 1 >= cnt) a2 = -1e30f;
        float e1 = sexp(a1);
        float e2 = sexp(a2);
        dsum += e1 + e2;
        u64 e12 = pk2(e1, e1), e22 = pk2(e2, e2);
#pragma unroll
        for (int p = 0; p < 4; p++)
            accp[p] = fma2(e22, l2[p], fma2(e12, l1[p], accp[p]));
    }
    if (i < maxc) {
        u64 p = d_sadj[sbase + i];
        int src1 = (int)(u32)p; float ea1 = __uint_as_float((u32)(p >> 32));
        const float* r1 = d_xl2 + (size_t)src1 * 128;
        ulonglong2 l1a = *(const ulonglong2*)(r1 + c0a);
        ulonglong2 l1b = *(const ulonglong2*)(r1 + c0b);
        u64 l1[4] = {l1a.x, l1a.y, l1b.x, l1b.y};
        u64 ev1 = pk2(ea1, ea1);
        u64 lg1 = 0ull;
#pragma unroll
        for (int q = 0; q < 4; q++) lg1 = gat2(l1[q], xr2v[q], we2[q], at2[q], ev1, c06, c04, lg1);
        float lo1, hi1; upk2(lg1, lo1, hi1);
        float a1 = lo1 + hi1;
        a1 += __shfl_xor_sync(0xffffffffu, a1, 1);
        a1 += __shfl_xor_sync(0xffffffffu, a1, 2);
        a1 += __shfl_xor_sync(0xffffffffu, a1, 4);
        a1 += __shfl_xor_sync(0xffffffffu, a1, 8);
        if (i >= cnt) a1 = -1e30f;
        float e1 = sexp(a1);
        dsum += e1;
        u64 e12 = pk2(e1, e1);
#pragma unroll
        for (int q = 0; q < 4; q++)
            accp[q] = fma2(e12, l1[q], accp[q]);
    }

    float inv = 1.f / (dsum + 1e-16f);
    float o[8];
#pragma unroll
    for (int p = 0; p < 4; p++) upk2(accp[p], o[2 * p], o[2 * p + 1]);
    float4 bA = __ldg((const float4*)(b2 + c0a));
    float4 bB = __ldg((const float4*)(b2 + c0b));
    o[0] = o[0] * inv + bA.x; o[1] = o[1] * inv + bA.y;
    o[2] = o[2] * inv + bA.z; o[3] = o[3] * inv + bA.w;
    o[4] = o[4] * inv + bB.x; o[5] = o[5] * inv + bB.y;
    o[6] = o[6] * inv + bB.z; o[7] = o[7] * inv + bB.w;

    // LayerNorm(128) across the 16-lane half
    float s = 0.f, s2 = 0.f;
#pragma unroll
    for (int j = 0; j < 8; j++) { s += o[j]; s2 += o[j] * o[j]; }
#pragma unroll
    for (int d = 8; d >= 1; d >>= 1) {
        s  += __shfl_xor_sync(0xffffffffu, s, d);
        s2 += __shfl_xor_sync(0xffffffffu, s2, d);
    }
    float mu = s * (1.f / 128.f);
    float var = s2 * (1.f / 128.f) - mu * mu;
    float rstd = rsqrtf(var + 1e-5f);
    float4 gA = __ldg((const float4*)(g2 + c0a));
    float4 gB = __ldg((const float4*)(g2 + c0b));
    float4 tA = __ldg((const float4*)(beta2 + c0a));
    float4 tB = __ldg((const float4*)(beta2 + c0b));
    float y[8];
    y[0] = (o[0]-mu)*rstd*gA.x + tA.x; y[1] = (o[1]-mu)*rstd*gA.y + tA.y;
    y[2] = (o[2]-mu)*rstd*gA.z + tA.z; y[3] = (o[3]-mu)*rstd*gA.w + tA.w;
    y[4] = (o[4]-mu)*rstd*gB.x + tB.x; y[5] = (o[5]-mu)*rstd*gB.y + tB.y;
    y[6] = (o[6]-mu)*rstd*gB.z + tB.z; y[7] = (o[7]-mu)*rstd*gB.w + tB.w;
#pragma unroll
    for (int j = 0; j < 8; j++) y[j] = (y[j] > 0.f) ? y[j] : (__expf(y[j]) - 1.f);
    float* ph = d_h2 + (size_t)n * 128;
    *(float4*)(ph + c0a) = make_float4(y[0], y[1], y[2], y[3]);
    *(float4*)(ph + c0b) = make_float4(y[4], y[5], y[6], y[7]);
}

// pooling: block of 128 threads handles 32 consecutive nodes (batch is sorted)
__global__ void k_pool(const int* __restrict__ batch) {
    __shared__ int s_b[32];
    int n0 = blockIdx.x * 32;
    int tid = threadIdx.x;
    if (tid < 32) {
        int n = n0 + tid;
        s_b[tid] = (n < NN) ? batch[n] : -1;
    }
    __syncthreads();
    int c = tid;
    float acc = 0.f;
    int cur = s_b[0];
    for (int j = 0; j < 32; j++) {
        int n = n0 + j;
        if (n >= NN) break;
        int g = s_b[j];
        if (g != cur) {
            atomicAdd(&d_pool[cur * 128 + c], acc);
            acc = 0.f;
            cur = g;
        }
        acc += d_h2[(size_t)n * 128 + c];
    }
    atomicAdd(&d_pool[cur * 128 + c], acc);
    if (tid == 0) {
        int cg = s_b[0];
        float ct = 0.f;
        for (int j = 0; j < 32; j++) {
            int n = n0 + j;
            if (n >= NN) break;
            int g = s_b[j];
            if (g != cg) { atomicAdd(&d_cnt[cg], ct); ct = 0.f; cg = g; }
            ct += 1.f;
        }
        atomicAdd(&d_cnt[cg], ct);
    }
}

__global__ void k_pooldiv(float* __restrict__ out) {
    int g = blockIdx.x, c = threadIdx.x;
    out[g * 128 + c] = d_pool[g * 128 + c] / fmaxf(d_cnt[g], 1.f);
    d_pool[g * 128 + c] = 0.f;      // reset for next replay
    if (c == 0) d_cnt[g] = 0.f;
}

// ---------------------------------------------------------------------------
extern "C" void kernel_launch(void* const* d_in, const int* in_sizes, int n_in,
                              void* d_out, int out_size) {
    const float* x     = (const float*)d_in[0];
    const int*   ei    = (const int*)  d_in[1];
    const float* ea    = (const float*)d_in[2];
    const int*   batch = (const int*)  d_in[3];
    const float* Wl1   = (const float*)d_in[4];
    const float* Wr1   = (const float*)d_in[5];
    const float* We1   = (const float*)d_in[6];
    const float* att1  = (const float*)d_in[7];
    const float* b1    = (const float*)d_in[8];
    const float* g1    = (const float*)d_in[9];
    const float* beta1 = (const float*)d_in[10];
    const float* Wl2   = (const float*)d_in[11];
    const float* Wr2   = (const float*)d_in[12];
    const float* We2   = (const float*)d_in[13];
    const float* att2  = (const float*)d_in[14];
    const float* b2    = (const float*)d_in[15];
    const float* g2    = (const float*)d_in[16];
    const float* beta2 = (const float*)d_in[17];
    float* out = (float*)d_out;

    k_gemm1<<<NN / 4, 256>>>(x, Wl1);                                 // #1
    k_fill<<<(NE / 2 + 255) / 256, 256>>>(ei, ea, 0, NE / 2);         // #2
    k_fill<<<(NE / 2 + 255) / 256, 256>>>(ei, ea, NE / 2, NE);        // #3
    k_fagg1<<<(NN + 7) / 8, 256>>>(x, Wr1, We1, att1, b1, g1, beta1); // #4 (profiled)
    k_gemm2<<<(NN + 127) / 128, 512>>>(Wl2, Wr2);                     // #5
    k_fagg2<<<NN / 16, 256>>>(We2, att2, b2, g2, beta2);              // #6
    k_pool<<<(NN + 31) / 32, 128>>>(batch);                           // #7
    k_pooldiv<<<NG, 128>>>(out);                                      // #8
}

// round 17
// speedup vs baseline: 1.2811x; 1.0169x over previous
#include <cuda_runtime.h>
#include <cuda_bf16.h>
#include <math.h>

#define NN 50000
#define NE 800000
#define NG 64
#define SLOT 96

typedef unsigned long long u64;
typedef unsigned int u32;

// ------------------- scratch (device globals; zero-initialized at load) ----
__device__ u32   d_xl1p[(size_t)NN * 128];   // bf16x2-packed xl1 rows (512B/row)
__device__ float d_h1 [NN * 256];
__device__ float d_xl2[NN * 128];
__device__ float d_xr2[NN * 128];
__device__ float d_h2 [NN * 128];
__device__ float d_loopsum[NN];
__device__ int   d_cursor[NN];
__device__ u64   d_sadj[(size_t)NN * SLOT];   // packed (ea:f32 hi, src:i32 lo)
__device__ float d_pool[NG * 128];
__device__ float d_cnt[NG];

// ---------------- packed f32x2 helpers --------------------------------------
__device__ __forceinline__ u64 pk2(float lo, float hi) {
    u64 r; asm("mov.b64 %0, {%1,%2};" : "=l"(r) : "f"(lo), "f"(hi)); return r;
}
__device__ __forceinline__ void upk2(u64 v, float& lo, float& hi) {
    asm("mov.b64 {%0,%1}, %2;" : "=f"(lo), "=f"(hi) : "l"(v));
}
__device__ __forceinline__ u64 add2(u64 a, u64 b) {
    u64 d; asm("add.rn.f32x2 %0, %1, %2;" : "=l"(d) : "l"(a), "l"(b)); return d;
}
__device__ __forceinline__ u64 mul2(u64 a, u64 b) {
    u64 d; asm("mul.rn.f32x2 %0, %1, %2;" : "=l"(d) : "l"(a), "l"(b)); return d;
}
__device__ __forceinline__ u64 fma2(u64 a, u64 b, u64 c) {
    u64 d; asm("fma.rn.f32x2 %0, %1, %2, %3;" : "=l"(d) : "l"(a), "l"(b), "l"(c)); return d;
}
#define ABS2 0x7FFFFFFF7FFFFFFFull

// bf16x2 (u32) -> packed f32x2 (u64): lo = p<<16, hi = p & 0xFFFF0000
__device__ __forceinline__ u64 bf2f2(u32 p) {
    return ((u64)(p & 0xFFFF0000u) << 32) | (u64)(p << 16);
}

// packed GATv2 logit contribution: t = leaky(l + xr + eav*we); lg += t*at
__device__ __forceinline__ u64 gat2(u64 l, u64 xr, u64 we, u64 at, u64 eav2,
                                    u64 c06, u64 c04, u64 lg) {
    u64 t = add2(l, xr);
    t = fma2(eav2, we, t);
    u64 ab = t & ABS2;
    t = fma2(c04, ab, mul2(t, c06));    // = m>0 ? m : 0.2m
    return fma2(t, at, lg);
}

// safe exp: logits here are O(10); clamp is a never-hit overflow guard
__device__ __forceinline__ float sexp(float a) { return __expf(fminf(a, 80.f)); }

// ---------------------------------------------------------------------------
// gemm1: xl1 = x @ Wl1 (K=8), stored bf16x2-packed. 4 nodes/block, 256 thr.
__global__ void k_gemm1(const float* __restrict__ x, const float* __restrict__ Wl) {
    __shared__ float sx[32];
    int n0 = blockIdx.x * 4;
    int tid = threadIdx.x;
    if (tid < 32) sx[tid] = x[n0 * 8 + tid];
    __syncthreads();
    float w[8];
#pragma unroll
    for (int k = 0; k < 8; k++) w[k] = Wl[k * 256 + tid];
#pragma unroll
    for (int q = 0; q < 4; q++) {
        float a = 0.f;
#pragma unroll
        for (int k = 0; k < 8; k++) a += sx[q * 8 + k] * w[k];
        float b = __shfl_down_sync(0xffffffffu, a, 1);
        if ((tid & 1) == 0) {
            u32 pa = __bfloat16_as_ushort(__float2bfloat16(a));
            u32 pb = __bfloat16_as_ushort(__float2bfloat16(b));
            d_xl1p[(size_t)(n0 + q) * 128 + (tid >> 1)] = pa | (pb << 16);
        }
    }
}

// adjacency fill (half range per launch): slot table keyed by dst
__global__ void k_fill(const int* __restrict__ ei, const float* __restrict__ ea,
                       int e0, int e1) {
    int e = e0 + blockIdx.x * 256 + threadIdx.x;
    if (e < e1) {
        int dst = ei[NE + e];
        int src = ei[e];
        float v = ea[e];
        int p = atomicAdd(&d_cursor[dst], 1);
        if (p < SLOT)
            d_sadj[(size_t)dst * SLOT + p] =
                ((u64)__float_as_uint(v) << 32) | (u32)src;
        atomicAdd(&d_loopsum[dst], v);
    }
}

// ======== layer-1 FUSED, warp per node, bf16 xl1 gathers =====================
// Lane owns channels [lane*8, lane*8+8); head = lane>>3. One 16B load per edge
// per lane: 8 lanes x 16B = one full 128B line per head per instruction.
__global__ __launch_bounds__(256, 4) void
k_fagg1(const float* __restrict__ x,
        const float* __restrict__ Wr, const float* __restrict__ We,
        const float* __restrict__ att,
        const float* __restrict__ b1, const float* __restrict__ g1,
        const float* __restrict__ beta1) {
    int wid = threadIdx.x >> 5, lane = threadIdx.x & 31;
    int n = blockIdx.x * 8 + wid;

    int cnt = d_cursor[n];
    if (cnt > SLOT) cnt = SLOT;
    float loopv = d_loopsum[n] / fmaxf((float)cnt, 1.f);

    int c0 = lane * 8;

    // xr row: x[n] (8) @ Wr (8x256), this lane's 8 channels (fp32, then pack)
    float xv = (lane < 8) ? x[n * 8 + lane] : 0.f;
    float xr[8];
#pragma unroll
    for (int j = 0; j < 8; j++) xr[j] = 0.f;
#pragma unroll
    for (int k = 0; k < 8; k++) {
        float xk = __shfl_sync(0xffffffffu, xv, k);
        float4 wA = __ldg((const float4*)(Wr + k * 256 + c0));
        float4 wB = __ldg((const float4*)(Wr + k * 256 + c0 + 4));
        xr[0] += xk * wA.x; xr[1] += xk * wA.y; xr[2] += xk * wA.z; xr[3] += xk * wA.w;
        xr[4] += xk * wB.x; xr[5] += xk * wB.y; xr[6] += xk * wB.z; xr[7] += xk * wB.w;
    }
    u64 xr2[4];
#pragma unroll
    for (int p = 0; p < 4; p++) xr2[p] = pk2(xr[2 * p], xr[2 * p + 1]);

    ulonglong2 weL = *(const ulonglong2*)(We + c0);
    ulonglong2 weH = *(const ulonglong2*)(We + c0 + 4);
    ulonglong2 atL = *(const ulonglong2*)(att + c0);
    ulonglong2 atH = *(const ulonglong2*)(att + c0 + 4);
    u64 we2[4] = {weL.x, weL.y, weH.x, weH.y};
    u64 at2[4] = {atL.x, atL.y, atH.x, atH.y};
    const u64 c06 = pk2(0.6f, 0.6f), c04 = pk2(0.4f, 0.4f);

    const u32* xl1base = d_xl1p + lane * 4;

    // ---- self-loop initialization (unnormalized) ----
    u64 accp[4];
    float dsum;
    {
        uint4 raw = *(const uint4*)(xl1base + (size_t)n * 128);
        u64 sl[4] = {bf2f2(raw.x), bf2f2(raw.y), bf2f2(raw.z), bf2f2(raw.w)};
        u64 eav2 = pk2(loopv, loopv);
        u64 lg = 0ull;
#pragma unroll
        for (int p = 0; p < 4; p++) lg = gat2(sl[p], xr2[p], we2[p], at2[p], eav2, c06, c04, lg);
        float lo, hi; upk2(lg, lo, hi);
        float a = lo + hi;
        a += __shfl_xor_sync(0xffffffffu, a, 1);
        a += __shfl_xor_sync(0xffffffffu, a, 2);
        a += __shfl_xor_sync(0xffffffffu, a, 4);
        float e0 = sexp(a);
        dsum = e0;
        u64 e02 = pk2(e0, e0);
#pragma unroll
        for (int p = 0; p < 4; p++) accp[p] = mul2(e02, sl[p]);
    }

    const size_t sbase = (size_t)n * SLOT;
    int i = 0;
    // ---- pairs of edges (iterations fully independent) ----
    for (; i + 1 < cnt; i += 2) {
        ulonglong2 pp = *(const ulonglong2*)(d_sadj + sbase + i);
        int   src1 = (int)(u32)pp.x; float ea1 = __uint_as_float((u32)(pp.x >> 32));
        int   src2 = (int)(u32)pp.y; float ea2 = __uint_as_float((u32)(pp.y >> 32));
        uint4 raw1 = *(const uint4*)(xl1base + (size_t)src1 * 128);
        uint4 raw2 = *(const uint4*)(xl1base + (size_t)src2 * 128);
        u64 l1[4] = {bf2f2(raw1.x), bf2f2(raw1.y), bf2f2(raw1.z), bf2f2(raw1.w)};
        u64 l2[4] = {bf2f2(raw2.x), bf2f2(raw2.y), bf2f2(raw2.z), bf2f2(raw2.w)};
        u64 ev1 = pk2(ea1, ea1), ev2 = pk2(ea2, ea2);
        u64 lg1 = 0ull, lg2 = 0ull;
#pragma unroll
        for (int p = 0; p < 4; p++) {
            lg1 = gat2(l1[p], xr2[p], we2[p], at2[p], ev1, c06, c04, lg1);
            lg2 = gat2(l2[p], xr2[p], we2[p], at2[p], ev2, c06, c04, lg2);
        }
        float lo1, hi1, lo2, hi2;
        upk2(lg1, lo1, hi1); upk2(lg2, lo2, hi2);
        float a1 = lo1 + hi1, a2 = lo2 + hi2;
        a1 += __shfl_xor_sync(0xffffffffu, a1, 1);
        a2 += __shfl_xor_sync(0xffffffffu, a2, 1);
        a1 += __shfl_xor_sync(0xffffffffu, a1, 2);
        a2 += __shfl_xor_sync(0xffffffffu, a2, 2);
        a1 += __shfl_xor_sync(0xffffffffu, a1, 4);
        a2 += __shfl_xor_sync(0xffffffffu, a2, 4);
        float e1 = sexp(a1);
        float e2 = sexp(a2);
        dsum += e1 + e2;
        u64 e12 = pk2(e1, e1), e22 = pk2(e2, e2);
#pragma unroll
        for (int p = 0; p < 4; p++)
            accp[p] = fma2(e22, l2[p], fma2(e12, l1[p], accp[p]));
    }
    // ---- odd tail edge ----
    if (i < cnt) {
        u64 p = d_sadj[sbase + i];
        int src1 = (int)(u32)p; float ea1 = __uint_as_float((u32)(p >> 32));
        uint4 raw1 = *(const uint4*)(xl1base + (size_t)src1 * 128);
        u64 l1[4] = {bf2f2(raw1.x), bf2f2(raw1.y), bf2f2(raw1.z), bf2f2(raw1.w)};
        u64 ev1 = pk2(ea1, ea1);
        u64 lg1 = 0ull;
#pragma unroll
        for (int q = 0; q < 4; q++) lg1 = gat2(l1[q], xr2[q], we2[q], at2[q], ev1, c06, c04, lg1);
        float lo1, hi1; upk2(lg1, lo1, hi1);
        float a1 = lo1 + hi1;
        a1 += __shfl_xor_sync(0xffffffffu, a1, 1);
        a1 += __shfl_xor_sync(0xffffffffu, a1, 2);
        a1 += __shfl_xor_sync(0xffffffffu, a1, 4);
        float e1 = sexp(a1);
        dsum += e1;
        u64 e12 = pk2(e1, e1);
#pragma unroll
        for (int q = 0; q < 4; q++)
            accp[q] = fma2(e12, l1[q], accp[q]);
    }

    float inv = 1.f / (dsum + 1e-16f);
    float o[8];
#pragma unroll
    for (int p = 0; p < 4; p++) upk2(accp[p], o[2 * p], o[2 * p + 1]);
    float4 bA = __ldg((const float4*)(b1 + c0));
    float4 bB = __ldg((const float4*)(b1 + c0 + 4));
    o[0] = o[0] * inv + bA.x; o[1] = o[1] * inv + bA.y;
    o[2] = o[2] * inv + bA.z; o[3] = o[3] * inv + bA.w;
    o[4] = o[4] * inv + bB.x; o[5] = o[5] * inv + bB.y;
    o[6] = o[6] * inv + bB.z; o[7] = o[7] * inv + bB.w;

    // LayerNorm(256) across the warp
    float s = 0.f, s2 = 0.f;
#pragma unroll
    for (int j = 0; j < 8; j++) { s += o[j]; s2 += o[j] * o[j]; }
#pragma unroll
    for (int d = 16; d >= 1; d >>= 1) {
        s  += __shfl_xor_sync(0xffffffffu, s, d);
        s2 += __shfl_xor_sync(0xffffffffu, s2, d);
    }
    float mu = s * (1.f / 256.f);
    float var = s2 * (1.f / 256.f) - mu * mu;
    float rstd = rsqrtf(var + 1e-5f);
    float4 gA = __ldg((const float4*)(g1 + c0));
    float4 gB = __ldg((const float4*)(g1 + c0 + 4));
    float4 tA = __ldg((const float4*)(beta1 + c0));
    float4 tB = __ldg((const float4*)(beta1 + c0 + 4));
    float y[8];
    y[0] = (o[0]-mu)*rstd*gA.x + tA.x; y[1] = (o[1]-mu)*rstd*gA.y + tA.y;
    y[2] = (o[2]-mu)*rstd*gA.z + tA.z; y[3] = (o[3]-mu)*rstd*gA.w + tA.w;
    y[4] = (o[4]-mu)*rstd*gB.x + tB.x; y[5] = (o[5]-mu)*rstd*gB.y + tB.y;
    y[6] = (o[6]-mu)*rstd*gB.z + tB.z; y[7] = (o[7]-mu)*rstd*gB.w + tB.w;
#pragma unroll
    for (int j = 0; j < 8; j++) y[j] = (y[j] > 0.f) ? y[j] : (__expf(y[j]) - 1.f);
    float4* ph = (float4*)(d_h1 + (size_t)n * 256 + c0);
    ph[0] = make_float4(y[0], y[1], y[2], y[3]);
    ph[1] = make_float4(y[4], y[5], y[6], y[7]);
}

// ======== GEMM2 via tf32 mma.sync, SMEM-staged + reg prefetch ===============
__device__ __forceinline__ u32 f2tf(float f) {
    u32 u;
    asm("cvt.rna.tf32.f32 %0, %1;" : "=r"(u) : "f"(f));
    return u;
}
__device__ __forceinline__ void mma_tf32(float* d, const u32* a, u32 b0, u32 b1) {
    asm("mma.sync.aligned.m16n8k8.row.col.f32.tf32.tf32.f32 "
        "{%0,%1,%2,%3}, {%4,%5,%6,%7}, {%8,%9}, {%0,%1,%2,%3};"
        : "+f"(d[0]), "+f"(d[1]), "+f"(d[2]), "+f"(d[3])
        : "r"(a[0]), "r"(a[1]), "r"(a[2]), "r"(a[3]), "r"(b0), "r"(b1));
}

#define GK 16
__global__ __launch_bounds__(512) void
k_gemm2(const float* __restrict__ Wl, const float* __restrict__ Wr) {
    __shared__ u32 sA[128][20];
    __shared__ u32 sB[GK][264];
    int tid = threadIdx.x;
    int w = tid >> 5, lane = tid & 31;
    int gid = lane >> 2, tig = lane & 3;
    int mgrp = w >> 2, ngrp = w & 3;
    int row0 = blockIdx.x * 128;
    int wm0 = mgrp * 32;
    int wn0 = ngrp * 64;

    float d[2][8][4];
#pragma unroll
    for (int mt = 0; mt < 2; mt++)
#pragma unroll
        for (int nt = 0; nt < 8; nt++)
#pragma unroll
            for (int q = 0; q < 4; q++) d[mt][nt][q] = 0.f;

    int ar = tid >> 2, akq = tid & 3;
    int gr = min(row0 + ar, NN - 1);
    const float4* aptr = (const float4*)(d_h1 + (size_t)gr * 256 + akq * 4);
    int kr0 = tid >> 6,         cq0 = tid & 63;
    int kr1 = (tid + 512) >> 6, cq1 = (tid + 512) & 63;
    const float* bsrc0 = (cq0 < 32) ? (Wl + kr0 * 128 + cq0 * 4)
                                    : (Wr + kr0 * 128 + (cq0 - 32) * 4);
    const float* bsrc1 = (cq1 < 32) ? (Wl + kr1 * 128 + cq1 * 4)
                                    : (Wr + kr1 * 128 + (cq1 - 32) * 4);

    float4 va = aptr[0];
    float4 vb0 = *(const float4*)bsrc0;
    float4 vb1 = *(const float4*)bsrc1;

    for (int k0 = 0; k0 < 256; k0 += GK) {
        sA[ar][akq * 4 + 0] = f2tf(va.x);
        sA[ar][akq * 4 + 1] = f2tf(va.y);
        sA[ar][akq * 4 + 2] = f2tf(va.z);
        sA[ar][akq * 4 + 3] = f2tf(va.w);
        sB[kr0][cq0 * 4 + 0] = f2tf(vb0.x);
        sB[kr0][cq0 * 4 + 1] = f2tf(vb0.y);
        sB[kr0][cq0 * 4 + 2] = f2tf(vb0.z);
        sB[kr0][cq0 * 4 + 3] = f2tf(vb0.w);
        sB[kr1][cq1 * 4 + 0] = f2tf(vb1.x);
        sB[kr1][cq1 * 4 + 1] = f2tf(vb1.y);
        sB[kr1][cq1 * 4 + 2] = f2tf(vb1.z);
        sB[kr1][cq1 * 4 + 3] = f2tf(vb1.w);
        __syncthreads();
        if (k0 + GK < 256) {
            va  = aptr[(k0 + GK) >> 2];
            vb0 = *(const float4*)(bsrc0 + (size_t)(k0 + GK) * 128);
            vb1 = *(const float4*)(bsrc1 + (size_t)(k0 + GK) * 128);
        }
#pragma unroll
        for (int kk = 0; kk < GK; kk += 8) {
            u32 a[2][4];
            a[0][0] = sA[wm0 + gid][kk + tig];
            a[0][1] = sA[wm0 + gid + 8][kk + tig];
            a[0][2] = sA[wm0 + gid][kk + tig + 4];
            a[0][3] = sA[wm0 + gid + 8][kk + tig + 4];
            a[1][0] = sA[wm0 + 16 + gid][kk + tig];
            a[1][1] = sA[wm0 + 24 + gid][kk + tig];
            a[1][2] = sA[wm0 + 16 + gid][kk + tig + 4];
            a[1][3] = sA[wm0 + 24 + gid][kk + tig + 4];
#pragma unroll
            for (int nt = 0; nt < 8; nt++) {
                int c = wn0 + nt * 8 + gid;
                u32 b0 = sB[kk + tig][c];
                u32 b1 = sB[kk + tig + 4][c];
                mma_tf32(d[0][nt], a[0], b0, b1);
                mma_tf32(d[1][nt], a[1], b0, b1);
            }
        }
        __syncthreads();
    }

    float* OUT = (wn0 < 128) ? d_xl2 : d_xr2;
#pragma unroll
    for (int mt = 0; mt < 2; mt++) {
        int rA = row0 + wm0 + mt * 16 + gid;
        int rB = rA + 8;
#pragma unroll
        for (int nt = 0; nt < 8; nt++) {
            int cc = (wn0 + nt * 8 + 2 * tig) & 127;
            if (rA < NN)
                *(float2*)(OUT + (size_t)rA * 128 + cc) = make_float2(d[mt][nt][0], d[mt][nt][1]);
            if (rB < NN)
                *(float2*)(OUT + (size_t)rB * 128 + cc) = make_float2(d[mt][nt][2], d[mt][nt][3]);
        }
    }
}

// ======== layer-2 FUSED: 2 nodes per warp, COALESCED split-channel layout ===
// Lane owns channels [lane16*4,+4) and [64+lane16*4,+4) of node (wid*2+half).
__global__ __launch_bounds__(256, 4) void
k_fagg2(const float* __restrict__ We, const float* __restrict__ att,
        const float* __restrict__ b2, const float* __restrict__ g2,
        const float* __restrict__ beta2) {
    int wid = threadIdx.x >> 5, lane = threadIdx.x & 31;
    int half = lane >> 4, lane16 = lane & 15;
    int n = blockIdx.x * 16 + wid * 2 + half;

    int cnt = d_cursor[n];
    if (cnt > SLOT) cnt = SLOT;
    float loopv = d_loopsum[n] / fmaxf((float)cnt, 1.f);
    if (lane16 == 0) { d_cursor[n] = 0; d_loopsum[n] = 0.f; }

    int c0a = lane16 * 4;
    int c0b = 64 + lane16 * 4;
    const float* rowx = d_xr2 + (size_t)n * 128;
    ulonglong2 xrA = *(const ulonglong2*)(rowx + c0a);
    ulonglong2 xrB = *(const ulonglong2*)(rowx + c0b);
    u64 xr2v[4] = {xrA.x, xrA.y, xrB.x, xrB.y};
    ulonglong2 weA = *(const ulonglong2*)(We + c0a);
    ulonglong2 weB = *(const ulonglong2*)(We + c0b);
    ulonglong2 atA = *(const ulonglong2*)(att + c0a);
    ulonglong2 atB = *(const ulonglong2*)(att + c0b);
    u64 we2[4] = {weA.x, weA.y, weB.x, weB.y};
    u64 at2[4] = {atA.x, atA.y, atB.x, atB.y};
    const u64 c06 = pk2(0.6f, 0.6f), c04 = pk2(0.4f, 0.4f);

    // self-loop init (unnormalized)
    const float* rown = d_xl2 + (size_t)n * 128;
    ulonglong2 s0 = *(const ulonglong2*)(rown + c0a);
    ulonglong2 s1 = *(const ulonglong2*)(rown + c0b);
    u64 sl[4] = {s0.x, s0.y, s1.x, s1.y};
    u64 accp[4];
    float dsum;
    {
        u64 ev = pk2(loopv, loopv);
        u64 lg = 0ull;
#pragma unroll
        for (int p = 0; p < 4; p++) lg = gat2(sl[p], xr2v[p], we2[p], at2[p], ev, c06, c04, lg);
        float lo, hi; upk2(lg, lo, hi);
        float a = lo + hi;
        a += __shfl_xor_sync(0xffffffffu, a, 1);
        a += __shfl_xor_sync(0xffffffffu, a, 2);
        a += __shfl_xor_sync(0xffffffffu, a, 4);
        a += __shfl_xor_sync(0xffffffffu, a, 8);
        float e0 = sexp(a);
        dsum = e0;
        u64 e02 = pk2(e0, e0);
#pragma unroll
        for (int p = 0; p < 4; p++) accp[p] = mul2(e02, sl[p]);
    }

    // uniform loop bound across the warp (both nodes)
    int cnto = __shfl_xor_sync(0xffffffffu, cnt, 16);
    int maxc = max(cnt, cnto);

    const size_t sbase = (size_t)n * SLOT;
    int i = 0;
    for (; i + 1 < maxc; i += 2) {
        ulonglong2 pp = *(const ulonglong2*)(d_sadj + sbase + i);
        int   src1 = (int)(u32)pp.x; float ea1 = __uint_as_float((u32)(pp.x >> 32));
        int   src2 = (int)(u32)pp.y; float ea2 = __uint_as_float((u32)(pp.y >> 32));
        const float* r1 = d_xl2 + (size_t)src1 * 128;
        const float* r2 = d_xl2 + (size_t)src2 * 128;
        ulonglong2 l1a = *(const ulonglong2*)(r1 + c0a);
        ulonglong2 l1b = *(const ulonglong2*)(r1 + c0b);
        ulonglong2 l2a = *(const ulonglong2*)(r2 + c0a);
        ulonglong2 l2b = *(const ulonglong2*)(r2 + c0b);
        u64 l1[4] = {l1a.x, l1a.y, l1b.x, l1b.y};
        u64 l2[4] = {l2a.x, l2a.y, l2b.x, l2b.y};
        u64 ev1 = pk2(ea1, ea1), ev2 = pk2(ea2, ea2);
        u64 lg1 = 0ull, lg2 = 0ull;
#pragma unroll
        for (int p = 0; p < 4; p++) {
            lg1 = gat2(l1[p], xr2v[p], we2[p], at2[p], ev1, c06, c04, lg1);
            lg2 = gat2(l2[p], xr2v[p], we2[p], at2[p], ev2, c06, c04, lg2);
        }
        float lo1, hi1, lo2, hi2;
        upk2(lg1, lo1, hi1); upk2(lg2, lo2, hi2);
        float a1 = lo1 + hi1, a2 = lo2 + hi2;
        a1 += __shfl_xor_sync(0xffffffffu, a1, 1);
        a2 += __shfl_xor_sync(0xffffffffu, a2, 1);
        a1 += __shfl_xor_sync(0xffffffffu, a1, 2);
        a2 += __shfl_xor_sync(0xffffffffu, a2, 2);
        a1 += __shfl_xor_sync(0xffffffffu, a1, 4);
        a2 += __shfl_xor_sync(0xffffffffu, a2, 4);
        a1 += __shfl_xor_sync(0xffffffffu, a1, 8);
        a2 += __shfl_xor_sync(0xffffffffu, a2, 8);
        // mask edges beyond this node's own count (exp underflows to 0)
        if (i >= cnt)     a1 = -1e30f;
        if (i + 1 >= cnt) a2 = -1e30f;
        float e1 = sexp(a1);
        float e2 = sexp(a2);
        dsum += e1 + e2;
        u64 e12 = pk2(e1, e1), e22 = pk2(e2, e2);
#pragma unroll
        for (int p = 0; p < 4; p++)
            accp[p] = fma2(e22, l2[p], fma2(e12, l1[p], accp[p]));
    }
    if (i < maxc) {
        u64 p = d_sadj[sbase + i];
        int src1 = (int)(u32)p; float ea1 = __uint_as_float((u32)(p >> 32));
        const float* r1 = d_xl2 + (size_t)src1 * 128;
        ulonglong2 l1a = *(const ulonglong2*)(r1 + c0a);
        ulonglong2 l1b = *(const ulonglong2*)(r1 + c0b);
        u64 l1[4] = {l1a.x, l1a.y, l1b.x, l1b.y};
        u64 ev1 = pk2(ea1, ea1);
        u64 lg1 = 0ull;
#pragma unroll
        for (int q = 0; q < 4; q++) lg1 = gat2(l1[q], xr2v[q], we2[q], at2[q], ev1, c06, c04, lg1);
        float lo1, hi1; upk2(lg1, lo1, hi1);
        float a1 = lo1 + hi1;
        a1 += __shfl_xor_sync(0xffffffffu, a1, 1);
        a1 += __shfl_xor_sync(0xffffffffu, a1, 2);
        a1 += __shfl_xor_sync(0xffffffffu, a1, 4);
        a1 += __shfl_xor_sync(0xffffffffu, a1, 8);
        if (i >= cnt) a1 = -1e30f;
        float e1 = sexp(a1);
        dsum += e1;
        u64 e12 = pk2(e1, e1);
#pragma unroll
        for (int q = 0; q < 4; q++)
            accp[q] = fma2(e12, l1[q], accp[q]);
    }

    float inv = 1.f / (dsum + 1e-16f);
    float o[8];
#pragma unroll
    for (int p = 0; p < 4; p++) upk2(accp[p], o[2 * p], o[2 * p + 1]);
    float4 bA = __ldg((const float4*)(b2 + c0a));
    float4 bB = __ldg((const float4*)(b2 + c0b));
    o[0] = o[0] * inv + bA.x; o[1] = o[1] * inv + bA.y;
    o[2] = o[2] * inv + bA.z; o[3] = o[3] * inv + bA.w;
    o[4] = o[4] * inv + bB.x; o[5] = o[5] * inv + bB.y;
    o[6] = o[6] * inv + bB.z; o[7] = o[7] * inv + bB.w;

    // LayerNorm(128) across the 16-lane half
    float s = 0.f, s2 = 0.f;
#pragma unroll
    for (int j = 0; j < 8; j++) { s += o[j]; s2 += o[j] * o[j]; }
#pragma unroll
    for (int d = 8; d >= 1; d >>= 1) {
        s  += __shfl_xor_sync(0xffffffffu, s, d);
        s2 += __shfl_xor_sync(0xffffffffu, s2, d);
    }
    float mu = s * (1.f / 128.f);
    float var = s2 * (1.f / 128.f) - mu * mu;
    float rstd = rsqrtf(var + 1e-5f);
    float4 gA = __ldg((const float4*)(g2 + c0a));
    float4 gB = __ldg((const float4*)(g2 + c0b));
    float4 tA = __ldg((const float4*)(beta2 + c0a));
    float4 tB = __ldg((const float4*)(beta2 + c0b));
    float y[8];
    y[0] = (o[0]-mu)*rstd*gA.x + tA.x; y[1] = (o[1]-mu)*rstd*gA.y + tA.y;
    y[2] = (o[2]-mu)*rstd*gA.z + tA.z; y[3] = (o[3]-mu)*rstd*gA.w + tA.w;
    y[4] = (o[4]-mu)*rstd*gB.x + tB.x; y[5] = (o[5]-mu)*rstd*gB.y + tB.y;
    y[6] = (o[6]-mu)*rstd*gB.z + tB.z; y[7] = (o[7]-mu)*rstd*gB.w + tB.w;
#pragma unroll
    for (int j = 0; j < 8; j++) y[j] = (y[j] > 0.f) ? y[j] : (__expf(y[j]) - 1.f);
    float* ph = d_h2 + (size_t)n * 128;
    *(float4*)(ph + c0a) = make_float4(y[0], y[1], y[2], y[3]);
    *(float4*)(ph + c0b) = make_float4(y[4], y[5], y[6], y[7]);
}

// pooling: block of 128 threads handles 32 consecutive nodes (batch is sorted)
__global__ void k_pool(const int* __restrict__ batch) {
    __shared__ int s_b[32];
    int n0 = blockIdx.x * 32;
    int tid = threadIdx.x;
    if (tid < 32) {
        int n = n0 + tid;
        s_b[tid] = (n < NN) ? batch[n] : -1;
    }
    __syncthreads();
    int c = tid;
    float acc = 0.f;
    int cur = s_b[0];
    for (int j = 0; j < 32; j++) {
        int n = n0 + j;
        if (n >= NN) break;
        int g = s_b[j];
        if (g != cur) {
            atomicAdd(&d_pool[cur * 128 + c], acc);
            acc = 0.f;
            cur = g;
        }
        acc += d_h2[(size_t)n * 128 + c];
    }
    atomicAdd(&d_pool[cur * 128 + c], acc);
    if (tid == 0) {
        int cg = s_b[0];
        float ct = 0.f;
        for (int j = 0; j < 32; j++) {
            int n = n0 + j;
            if (n >= NN) break;
            int g = s_b[j];
            if (g != cg) { atomicAdd(&d_cnt[cg], ct); ct = 0.f; cg = g; }
            ct += 1.f;
        }
        atomicAdd(&d_cnt[cg], ct);
    }
}

__global__ void k_pooldiv(float* __restrict__ out) {
    int g = blockIdx.x, c = threadIdx.x;
    out[g * 128 + c] = d_pool[g * 128 + c] / fmaxf(d_cnt[g], 1.f);
    d_pool[g * 128 + c] = 0.f;      // reset for next replay
    if (c == 0) d_cnt[g] = 0.f;
}

// ---------------------------------------------------------------------------
extern "C" void kernel_launch(void* const* d_in, const int* in_sizes, int n_in,
                              void* d_out, int out_size) {
    const float* x     = (const float*)d_in[0];
    const int*   ei    = (const int*)  d_in[1];
    const float* ea    = (const float*)d_in[2];
    const int*   batch = (const int*)  d_in[3];
    const float* Wl1   = (const float*)d_in[4];
    const float* Wr1   = (const float*)d_in[5];
    const float* We1   = (const float*)d_in[6];
    const float* att1  = (const float*)d_in[7];
    const float* b1    = (const float*)d_in[8];
    const float* g1    = (const float*)d_in[9];
    const float* beta1 = (const float*)d_in[10];
    const float* Wl2   = (const float*)d_in[11];
    const float* Wr2   = (const float*)d_in[12];
    const float* We2   = (const float*)d_in[13];
    const float* att2  = (const float*)d_in[14];
    const float* b2    = (const float*)d_in[15];
    const float* g2    = (const float*)d_in[16];
    const float* beta2 = (const float*)d_in[17];
    float* out = (float*)d_out;

    k_gemm1<<<NN / 4, 256>>>(x, Wl1);                                 // #1
    k_fill<<<(NE / 2 + 255) / 256, 256>>>(ei, ea, 0, NE / 2);         // #2
    k_fill<<<(NE / 2 + 255) / 256, 256>>>(ei, ea, NE / 2, NE);        // #3
    k_fagg1<<<(NN + 7) / 8, 256>>>(x, Wr1, We1, att1, b1, g1, beta1); // #4 (profiled)
    k_gemm2<<<(NN + 127) / 128, 512>>>(Wl2, Wr2);                     // #5
    k_fagg2<<<NN / 16, 256>>>(We2, att2, b2, g2, beta2);              // #6
    k_pool<<<(NN + 31) / 32, 128>>>(batch);                           // #7
    k_pooldiv<<<NG, 128>>>(out);                                      // #8
}